// round 8
// baseline (speedup 1.0000x reference)
#include <cuda_runtime.h>
#include <math.h>
#include <stdint.h>

// ---------------- problem constants ----------------
#define BSZ    4
#define CIN    3
#define IMG    224
#define PATCH  16
#define DMODEL 384
#define DEPTH  4
#define NHEAD  8
#define HD     48
#define MLPD   1536
#define NCLS   5
#define TSTEPS 25
#define NTOK   196
#define ROWS   (BSZ*NTOK) // 784
#define HP     14
#define BETAF  0.9f
#define EPSF   1e-5f
#define SCALEF 0.14433756729740643f  // 48^-0.5
#define NCHUNK 28                     // 196 = 7*28

// ---------------- device state ----------------
__device__ float g_h   [ROWS*DMODEL];
__device__ float g_y   [ROWS*DMODEL];
__device__ float g_xn  [ROWS*DMODEL];
__device__ float g_q   [ROWS*DMODEL];
__device__ float g_k   [ROWS*DMODEL];
__device__ float g_v   [ROWS*DMODEL];
__device__ float g_o   [ROWS*DMODEL];
__device__ float g_s1  [ROWS*MLPD];
__device__ float g_pool[BSZ*DMODEL];
__device__ float g_mpe [ROWS*DMODEL];
__device__ float g_mq  [DEPTH*ROWS*DMODEL];
__device__ float g_mk  [DEPTH*ROWS*DMODEL];
__device__ float g_mv  [DEPTH*ROWS*DMODEL];
__device__ float g_m1  [DEPTH*ROWS*MLPD];
__device__ float g_m2  [DEPTH*ROWS*DMODEL];
__device__ float g_mh  [BSZ*NCLS];
__device__ float g_acc [BSZ*NCLS];

// software grid barrier state
__device__ unsigned g_arrive;
__device__ unsigned g_gen;

__device__ __forceinline__ void gsync()
{
    __syncthreads();
    if (threadIdx.x == 0) {
        __threadfence();
        unsigned gen = *(volatile unsigned*)&g_gen;
        unsigned nb = gridDim.x;
        if (atomicAdd(&g_arrive, 1u) == nb - 1u) {
            g_arrive = 0u;
            __threadfence();
            *(volatile unsigned*)&g_gen = gen + 1u;
        } else {
            while (*(volatile unsigned*)&g_gen == gen) { __nanosleep(64); }
        }
    }
    __syncthreads();
}

// ---------------- cp.async helpers ----------------
__device__ __forceinline__ void cp16(uint32_t saddr, const void* gptr, int src_bytes)
{
    asm volatile("cp.async.cg.shared.global [%0], [%1], 16, %2;\n"
                 :: "r"(saddr), "l"(gptr), "r"(src_bytes));
}
__device__ __forceinline__ void cp4(uint32_t saddr, const void* gptr)
{
    asm volatile("cp.async.ca.shared.global [%0], [%1], 4;\n"
                 :: "r"(saddr), "l"(gptr));
}
__device__ __forceinline__ void cp_commit()
{
    asm volatile("cp.async.commit_group;\n");
}
template<int N>
__device__ __forceinline__ void cp_wait()
{
    asm volatile("cp.async.wait_group %0;\n" :: "n"(N));
}

// ---------------- shared memory union ----------------
struct SmemU {
    union {
        float patch[CIN*PATCH*PATCH];                       // conv: 3072 B
        struct {
            float As[2][64][16];                            // [buf][m][k] 8 KB
            float Bs[2][16][64];                            // [buf][k][n] 8 KB
        } g;                                                // gemm: 16 KB
        struct {
            unsigned long long qcb[NCHUNK];
            unsigned long long kbv[NTOK];
            unsigned long long vbv[NTOK];
            unsigned char at[NCHUNK][NTOK];
        } a;                                                // attn: ~8.9 KB
    };
};

// ---------------- gemm 64x64 tile, 4x4 microtile, cp.async double-buffered ----------------
// serial-k single FMA chain per output (bit-exact vs XLA:CPU / Eigen)
// MODE 0: LIF -> spike   MODE 1: yout += acc   MODE 2: LIF -> yout += spike
template<int MODE>
__device__ __forceinline__ void gemm_tile64(SmemU* sm,
        const float* __restrict__ A, const float* __restrict__ W,
        int N, int K, int bm, int bn,
        const float* __restrict__ scale, const float* __restrict__ bias,
        float* __restrict__ mem, float* __restrict__ spk, float* __restrict__ yout)
{
    const int tid = threadIdx.x;     // 256
    const int tx = tid & 15;
    const int ty = tid >> 4;
    const int row = tid >> 2;        // 0..63
    const int kc  = (tid & 3) << 2;  // 0,4,8,12

    // global srcs for the copy role of this thread
    const int ar = bm + row;
    const int a_ok = (ar < ROWS) ? 16 : 0;
    const float* aptr = A + (size_t)((ar < ROWS) ? ar : 0)*K + kc;
    const float* bptr = W + (size_t)(bn + row)*K + kc;

    // smem dsts
    uint32_t sA0 = (uint32_t)__cvta_generic_to_shared(&sm->g.As[0][row][kc]);
    uint32_t sA1 = (uint32_t)__cvta_generic_to_shared(&sm->g.As[1][row][kc]);
    // B scatter: element (row, kc+i) of W-tile -> Bs[buf][kc+i][row]
    uint32_t sB0 = (uint32_t)__cvta_generic_to_shared(&sm->g.Bs[0][kc][row]);
    uint32_t sB1 = (uint32_t)__cvta_generic_to_shared(&sm->g.Bs[1][kc][row]);

    float acc[4][4];
    #pragma unroll
    for (int i = 0; i < 4; i++)
        #pragma unroll
        for (int j = 0; j < 4; j++) acc[i][j] = 0.f;

    const int nch = K >> 4;
    // prefetch chunk 0
    cp16(sA0, aptr, a_ok);
    #pragma unroll
    for (int i = 0; i < 4; i++) cp4(sB0 + i*64*4, bptr + i);
    cp_commit();

    for (int c = 0; c < nch; c++) {
        const int buf = c & 1;
        if (c + 1 < nch) {
            uint32_t dA = (buf ? sA0 : sA1);
            uint32_t dB = (buf ? sB0 : sB1);
            const float* ap = aptr + (c+1)*16;
            const float* bp = bptr + (c+1)*16;
            cp16(dA, ap, a_ok);
            #pragma unroll
            for (int i = 0; i < 4; i++) cp4(dB + i*64*4, bp + i);
            cp_commit();
            cp_wait<1>();
        } else {
            cp_wait<0>();
        }
        __syncthreads();
        const float (*As)[16] = sm->g.As[buf];
        const float (*Bs)[64] = sm->g.Bs[buf];
        #pragma unroll
        for (int kk = 0; kk < 16; kk++) {   // strictly ascending k; single chain per output
            float a0 = As[ty*4+0][kk];
            float a1 = As[ty*4+1][kk];
            float a2 = As[ty*4+2][kk];
            float a3 = As[ty*4+3][kk];
            float4 b = *reinterpret_cast<const float4*>(&Bs[kk][tx*4]);
            acc[0][0]=__fmaf_rn(a0,b.x,acc[0][0]); acc[0][1]=__fmaf_rn(a0,b.y,acc[0][1]);
            acc[0][2]=__fmaf_rn(a0,b.z,acc[0][2]); acc[0][3]=__fmaf_rn(a0,b.w,acc[0][3]);
            acc[1][0]=__fmaf_rn(a1,b.x,acc[1][0]); acc[1][1]=__fmaf_rn(a1,b.y,acc[1][1]);
            acc[1][2]=__fmaf_rn(a1,b.z,acc[1][2]); acc[1][3]=__fmaf_rn(a1,b.w,acc[1][3]);
            acc[2][0]=__fmaf_rn(a2,b.x,acc[2][0]); acc[2][1]=__fmaf_rn(a2,b.y,acc[2][1]);
            acc[2][2]=__fmaf_rn(a2,b.z,acc[2][2]); acc[2][3]=__fmaf_rn(a2,b.w,acc[2][3]);
            acc[3][0]=__fmaf_rn(a3,b.x,acc[3][0]); acc[3][1]=__fmaf_rn(a3,b.y,acc[3][1]);
            acc[3][2]=__fmaf_rn(a3,b.z,acc[3][2]); acc[3][3]=__fmaf_rn(a3,b.w,acc[3][3]);
        }
        __syncthreads();
    }

    #pragma unroll
    for (int i = 0; i < 4; i++) {
        int m = bm + ty*4 + i;
        if (m >= ROWS) break;
        #pragma unroll
        for (int j = 0; j < 4; j++) {
            int n = bn + tx*4 + j;
            size_t idx = (size_t)m*N + n;
            float vv = acc[i][j];
            if (MODE == 1) {
                yout[idx] = __fadd_rn(yout[idx], vv);
            } else {
                vv = __fadd_rn(__fmul_rn(vv, scale[n]), bias[n]);
                float mm = __fadd_rn(__fmul_rn(BETAF, mem[idx]), vv);
                float s = (mm > 1.0f) ? 1.0f : 0.0f;
                mem[idx] = __fadd_rn(mm, -s);
                if (MODE == 0) spk[idx] = s;
                else           yout[idx] = __fadd_rn(yout[idx], s);
            }
        }
    }
}

// ---------------- layernorm row, XLA:CPU vectorized-reduce order ----------------
__device__ __forceinline__ void ln_row_warp(const float* __restrict__ rin,
        const float* __restrict__ g, const float* __restrict__ bta, float* __restrict__ out)
{
    const unsigned fm = 0xffffffffu;
    int lane = threadIdx.x & 31;
    float a = 0.f;
    if (lane < 4) {
        for (int t2 = 0; t2 < 96; t2++) a = __fadd_rn(a, rin[4*t2 + lane]);
    }
    float a0 = __shfl_sync(fm, a, 0), a1 = __shfl_sync(fm, a, 1);
    float a2 = __shfl_sync(fm, a, 2), a3 = __shfl_sync(fm, a, 3);
    float mean = __fdiv_rn(__fadd_rn(__fadd_rn(a0, a2), __fadd_rn(a1, a3)), 384.0f);

    float b = 0.f;
    if (lane < 4) {
        for (int t2 = 0; t2 < 96; t2++) {
            float d = __fadd_rn(rin[4*t2 + lane], -mean);
            b = __fadd_rn(b, __fmul_rn(d, d));
        }
    }
    float b0 = __shfl_sync(fm, b, 0), b1 = __shfl_sync(fm, b, 1);
    float b2 = __shfl_sync(fm, b, 2), b3 = __shfl_sync(fm, b, 3);
    float var = __fdiv_rn(__fadd_rn(__fadd_rn(b0, b2), __fadd_rn(b1, b3)), 384.0f);
    float inv = __fdiv_rn(1.0f, __fsqrt_rn(__fadd_rn(var, EPSF)));

    for (int d = lane; d < DMODEL; d += 32) {
        float dv = __fadd_rn(rin[d], -mean);
        out[d] = __fadd_rn(__fmul_rn(__fmul_rn(dv, inv), g[d]), bta[d]);
    }
}

// ---------------- zero helper ----------------
__device__ __forceinline__ void zero_arr(float* p, int n, int gtid, int nth)
{
    for (int i = gtid; i < n; i += nth) p[i] = 0.f;
}

// ---------------- the megakernel ----------------
__global__ void __launch_bounds__(256, 2) mega(
    const float* __restrict__ x,      const float* __restrict__ conv_w,
    const float* __restrict__ bn0_s,  const float* __restrict__ bn0_b,
    const float* __restrict__ pos,
    const float* __restrict__ Wq,     const float* __restrict__ bnq_s, const float* __restrict__ bnq_b,
    const float* __restrict__ Wk,     const float* __restrict__ bnk_s, const float* __restrict__ bnk_b,
    const float* __restrict__ Wv,     const float* __restrict__ bnv_s, const float* __restrict__ bnv_b,
    const float* __restrict__ Wo,
    const float* __restrict__ ln1_g,  const float* __restrict__ ln1_b,
    const float* __restrict__ W1,     const float* __restrict__ bn1_s, const float* __restrict__ bn1_b,
    const float* __restrict__ W2,     const float* __restrict__ bn2_s, const float* __restrict__ bn2_b,
    const float* __restrict__ ln2_g,  const float* __restrict__ ln2_b,
    const float* __restrict__ lnf_g,  const float* __restrict__ lnf_b,
    const float* __restrict__ head_w, const float* __restrict__ head_b,
    float* __restrict__ out)
{
    __shared__ SmemU sm;
    const int nb  = gridDim.x;
    const int tid = threadIdx.x;
    const int wrp = tid >> 5;
    const int gtid = blockIdx.x * 256 + tid;
    const int nth  = nb * 256;

    // ---- zero persistent state ----
    zero_arr(g_mpe, ROWS*DMODEL, gtid, nth);
    zero_arr(g_mq,  DEPTH*ROWS*DMODEL, gtid, nth);
    zero_arr(g_mk,  DEPTH*ROWS*DMODEL, gtid, nth);
    zero_arr(g_mv,  DEPTH*ROWS*DMODEL, gtid, nth);
    zero_arr(g_m1,  DEPTH*ROWS*MLPD, gtid, nth);
    zero_arr(g_m2,  DEPTH*ROWS*DMODEL, gtid, nth);
    zero_arr(g_mh,  BSZ*NCLS, gtid, nth);
    zero_arr(g_acc, BSZ*NCLS, gtid, nth);

    // ---- conv patch embed (timestep-invariant); Eigen tap order (kh, kw, c), c minor ----
    for (int item = blockIdx.x; item < ROWS; item += nb) {
        int b = item / NTOK, n = item % NTOK;
        int py = n / HP, px = n % HP;
        for (int idx = tid; idx < 768; idx += 256) {
            int c = idx >> 8; int rem = idx & 255; int i = rem >> 4; int j = rem & 15;
            sm.patch[idx] = x[(((size_t)b*CIN + c)*IMG + (py*PATCH + i))*IMG + (px*PATCH + j)];
        }
        __syncthreads();
        for (int d = tid; d < DMODEL; d += 256) {
            const float* wr = conv_w + (size_t)d*768;
            float acc = 0.f;
            for (int i = 0; i < PATCH; i++)
                for (int j = 0; j < PATCH; j++)
                    #pragma unroll
                    for (int c = 0; c < CIN; c++) {
                        int off = c*256 + i*16 + j;
                        acc = __fmaf_rn(sm.patch[off], wr[off], acc);
                    }
            g_h[((size_t)b*NTOK + n)*DMODEL + d] = __fadd_rn(__fmul_rn(acc, bn0_s[d]), bn0_b[d]);
        }
        __syncthreads();
    }
    gsync();

    // ---- timestep loop ----
    for (int t = 0; t < TSTEPS; t++) {
        // patch-embed LIF + pos
        for (int i = gtid; i < ROWS*DMODEL; i += nth) {
            float mm = __fadd_rn(__fmul_rn(BETAF, g_mpe[i]), g_h[i]);
            float s = (mm > 1.0f) ? 1.0f : 0.0f;
            g_mpe[i] = __fadd_rn(mm, -s);
            g_y[i] = __fadd_rn(s, pos[i % (NTOK*DMODEL)]);
        }
        gsync();

        for (int l = 0; l < DEPTH; l++) {
            const size_t wOff  = (size_t)l * DMODEL * DMODEL;
            const size_t w1Off = (size_t)l * MLPD * DMODEL;
            const size_t memD  = (size_t)l * ROWS * DMODEL;
            const size_t memM  = (size_t)l * ROWS * MLPD;
            const float* Wq_l = Wq + wOff;   const float* Wk_l = Wk + wOff;
            const float* Wv_l = Wv + wOff;   const float* Wo_l = Wo + wOff;
            const float* W1_l = W1 + w1Off;  const float* W2_l = W2 + w1Off;
            const float* qs = bnq_s + l*DMODEL, *qb2 = bnq_b + l*DMODEL;
            const float* ks = bnk_s + l*DMODEL, *kb2 = bnk_b + l*DMODEL;
            const float* vs = bnv_s + l*DMODEL, *vb2 = bnv_b + l*DMODEL;
            const float* m1s = bn1_s + l*MLPD,  *m1b = bn1_b + l*MLPD;
            const float* m2s = bn2_s + l*DMODEL, *m2b = bn2_b + l*DMODEL;

            // LN1 (warp per row)
            for (int row = blockIdx.x*8 + wrp; row < ROWS; row += nb*8)
                ln_row_warp(g_y + (size_t)row*DMODEL, ln1_g + l*DMODEL, ln1_b + l*DMODEL,
                            g_xn + (size_t)row*DMODEL);
            gsync();

            // QKV: 3 x (13x6)=234 tiles of 64x64
            for (int t5 = blockIdx.x; t5 < 234; t5 += nb) {
                int which = t5 / 78, s = t5 % 78;
                int bm = (s / 6) * 64, bn = (s % 6) * 64;
                if (which == 0)
                    gemm_tile64<0>(&sm, g_xn, Wq_l, DMODEL, DMODEL, bm, bn, qs, qb2, g_mq + memD, g_q, 0);
                else if (which == 1)
                    gemm_tile64<0>(&sm, g_xn, Wk_l, DMODEL, DMODEL, bm, bn, ks, kb2, g_mk + memD, g_k, 0);
                else
                    gemm_tile64<0>(&sm, g_xn, Wv_l, DMODEL, DMODEL, bm, bn, vs, vb2, g_mv + memD, g_v, 0);
            }
            gsync();

            // attention: exact integer counts + rounded serial-m einsum2
            for (int item = blockIdx.x; item < 7*32; item += nb) {
                int chunk = item % 7;
                int bh = item / 7;
                int b = bh >> 3, h = bh & 7;
                int n0 = chunk * NCHUNK;
                __syncthreads();
                for (int tt = tid; tt < NTOK*2 + NCHUNK; tt += 256) {
                    int which, n;
                    if (tt < NTOK)        { which = 1; n = tt; }
                    else if (tt < 2*NTOK) { which = 2; n = tt - NTOK; }
                    else                  { which = 0; n = n0 + (tt - 2*NTOK); }
                    const float* src = (which == 0 ? g_q : (which == 1 ? g_k : g_v))
                                       + ((size_t)(b*NTOK + n))*DMODEL + h*HD;
                    unsigned long long bits = 0ull;
                    #pragma unroll
                    for (int j = 0; j < HD; j++)
                        if (src[j] != 0.f) bits |= (1ull << j);
                    if (which == 0)      sm.a.qcb[n - n0] = bits;
                    else if (which == 1) sm.a.kbv[n] = bits;
                    else                 sm.a.vbv[n] = bits;
                }
                __syncthreads();
                for (int idx = tid; idx < NCHUNK*NTOK; idx += 256)
                    sm.a.at[idx/NTOK][idx%NTOK] =
                        (unsigned char)__popcll(sm.a.qcb[idx/NTOK] & sm.a.kbv[idx%NTOK]);
                __syncthreads();
                for (int it2 = tid; it2 < NCHUNK*HD; it2 += 256) {
                    int n = it2 / HD, d = it2 % HD;
                    const unsigned char* arow = sm.a.at[n];
                    float acc = 0.f;
                    for (int m = 0; m < NTOK; m++) {
                        float a = __fmul_rn((float)arow[m], SCALEF);
                        float vm = (float)((sm.a.vbv[m] >> d) & 1ull);
                        acc = __fmaf_rn(a, vm, acc);
                    }
                    g_o[((size_t)(b*NTOK + n0 + n))*DMODEL + h*HD + d] = acc;
                }
                __syncthreads();
            }
            gsync();

            // Wo residual: 78 tiles
            for (int t5 = blockIdx.x; t5 < 78; t5 += nb) {
                int bm = (t5 / 6) * 64, bn = (t5 % 6) * 64;
                gemm_tile64<1>(&sm, g_o, Wo_l, DMODEL, DMODEL, bm, bn, 0, 0, 0, 0, g_y);
            }
            gsync();

            // LN2
            for (int row = blockIdx.x*8 + wrp; row < ROWS; row += nb*8)
                ln_row_warp(g_y + (size_t)row*DMODEL, ln2_g + l*DMODEL, ln2_b + l*DMODEL,
                            g_xn + (size_t)row*DMODEL);
            gsync();

            // MLP1: 13x24 = 312 tiles
            for (int t5 = blockIdx.x; t5 < 312; t5 += nb) {
                int bm = (t5 / 24) * 64, bn = (t5 % 24) * 64;
                gemm_tile64<0>(&sm, g_xn, W1_l, MLPD, DMODEL, bm, bn, m1s, m1b, g_m1 + memM, g_s1, 0);
            }
            gsync();

            // MLP2: 78 tiles, K=1536
            for (int t5 = blockIdx.x; t5 < 78; t5 += nb) {
                int bm = (t5 / 6) * 64, bn = (t5 % 6) * 64;
                gemm_tile64<2>(&sm, g_s1, W2_l, DMODEL, MLPD, bm, bn, m2s, m2b, g_m2 + memD, 0, g_y);
            }
            gsync();
        }

        // final LN
        for (int row = blockIdx.x*8 + wrp; row < ROWS; row += nb*8)
            ln_row_warp(g_y + (size_t)row*DMODEL, lnf_g, lnf_b, g_xn + (size_t)row*DMODEL);
        gsync();

        // token-mean pool (serial over n, ascending — major-dim reduce order)
        for (int it = gtid; it < BSZ*DMODEL; it += nth) {
            int b = it / DMODEL, d = it % DMODEL;
            float acc = 0.f;
            for (int n = 0; n < NTOK; n++)
                acc = __fadd_rn(acc, g_xn[((size_t)(b*NTOK + n))*DMODEL + d]);
            g_pool[it] = __fdiv_rn(acc, 196.0f);
        }
        gsync();

        // head logits + LIF (block 0): Eigen serial-k FMA
        if (blockIdx.x == 0 && tid < BSZ*NCLS) {
            int b = tid / NCLS, c = tid % NCLS;
            float acc = 0.f;
            for (int d = 0; d < DMODEL; d++)
                acc = __fmaf_rn(g_pool[b*DMODEL + d], head_w[d*NCLS + c], acc);
            float inp = __fadd_rn(acc, head_b[c]);
            float mm = __fadd_rn(__fmul_rn(BETAF, g_mh[tid]), inp);
            float s = (mm > 1.0f) ? 1.0f : 0.0f;
            g_mh[tid] = __fadd_rn(mm, -s);
            g_acc[tid] += s;
        }
        gsync();
    }

    if (blockIdx.x == 0 && tid < BSZ*NCLS)
        out[tid] = __fdiv_rn(g_acc[tid], (float)TSTEPS);
}

// ---------------- host ----------------
extern "C" void kernel_launch(void* const* d_in, const int* in_sizes, int n_in,
                              void* d_out, int out_size)
{
    const float* x       = (const float*)d_in[0];
    const float* conv_w  = (const float*)d_in[1];
    const float* bn0_s   = (const float*)d_in[2];
    const float* bn0_b   = (const float*)d_in[3];
    const float* pos     = (const float*)d_in[4];
    const float* Wq      = (const float*)d_in[5];
    const float* bnq_s   = (const float*)d_in[6];
    const float* bnq_b   = (const float*)d_in[7];
    const float* Wk      = (const float*)d_in[8];
    const float* bnk_s   = (const float*)d_in[9];
    const float* bnk_b   = (const float*)d_in[10];
    const float* Wv      = (const float*)d_in[11];
    const float* bnv_s   = (const float*)d_in[12];
    const float* bnv_b   = (const float*)d_in[13];
    const float* Wo      = (const float*)d_in[14];
    const float* ln1_g   = (const float*)d_in[15];
    const float* ln1_b   = (const float*)d_in[16];
    const float* W1      = (const float*)d_in[17];
    const float* bn1_s   = (const float*)d_in[18];
    const float* bn1_b   = (const float*)d_in[19];
    const float* W2      = (const float*)d_in[20];
    const float* bn2_s   = (const float*)d_in[21];
    const float* bn2_b   = (const float*)d_in[22];
    const float* ln2_g   = (const float*)d_in[23];
    const float* ln2_b   = (const float*)d_in[24];
    const float* lnf_g   = (const float*)d_in[25];
    const float* lnf_b   = (const float*)d_in[26];
    const float* head_w  = (const float*)d_in[27];
    const float* head_b  = (const float*)d_in[28];
    float* out = (float*)d_out;

    int dev = 0;
    cudaGetDevice(&dev);
    int nsm = 0;
    cudaDeviceGetAttribute(&nsm, cudaDevAttrMultiProcessorCount, dev);
    int bpm = 0;
    cudaOccupancyMaxActiveBlocksPerMultiprocessor(&bpm, mega, 256, 0);
    if (bpm < 1) bpm = 1;
    if (bpm > 2) bpm = 2;
    int nblk = nsm * bpm;

    mega<<<nblk, 256>>>(x, conv_w, bn0_s, bn0_b, pos,
                        Wq, bnq_s, bnq_b, Wk, bnk_s, bnk_b, Wv, bnv_s, bnv_b, Wo,
                        ln1_g, ln1_b, W1, bn1_s, bn1_b, W2, bn2_s, bn2_b,
                        ln2_g, ln2_b, lnf_g, lnf_b, head_w, head_b, out);
}

// round 9
// speedup vs baseline: 1.0022x; 1.0022x over previous
#include <cuda_runtime.h>
#include <math.h>
#include <stdint.h>

// ---------------- problem constants ----------------
#define BSZ    4
#define CIN    3
#define IMG    224
#define PATCH  16
#define DMODEL 384
#define DEPTH  4
#define NHEAD  8
#define HD     48
#define MLPD   1536
#define NCLS   5
#define TSTEPS 25
#define NTOK   196
#define ROWS   (BSZ*NTOK) // 784
#define HP     14
#define BETAF  0.9f
#define EPSF   1e-5f
#define SCALEF 0.14433756729740643f  // 48^-0.5
#define NCHUNK 28                     // 196 = 7*28

// ---------------- device state ----------------
__device__ float g_h   [ROWS*DMODEL];
__device__ float g_y   [ROWS*DMODEL];
__device__ float g_xn  [ROWS*DMODEL];
__device__ float g_q   [ROWS*DMODEL];
__device__ float g_k   [ROWS*DMODEL];
__device__ float g_v   [ROWS*DMODEL];
__device__ float g_o   [ROWS*DMODEL];
__device__ float g_s1  [ROWS*MLPD];
__device__ float g_pool[BSZ*DMODEL];
__device__ float g_mpe [ROWS*DMODEL];
__device__ float g_mq  [DEPTH*ROWS*DMODEL];
__device__ float g_mk  [DEPTH*ROWS*DMODEL];
__device__ float g_mv  [DEPTH*ROWS*DMODEL];
__device__ float g_m1  [DEPTH*ROWS*MLPD];
__device__ float g_m2  [DEPTH*ROWS*DMODEL];
__device__ float g_mh  [BSZ*NCLS];
__device__ float g_acc [BSZ*NCLS];

// software grid barrier state
__device__ unsigned g_arrive;
__device__ unsigned g_gen;

__device__ __forceinline__ void gsync()
{
    __syncthreads();
    if (threadIdx.x == 0) {
        __threadfence();
        unsigned gen = *(volatile unsigned*)&g_gen;
        unsigned nb = gridDim.x;
        if (atomicAdd(&g_arrive, 1u) == nb - 1u) {
            g_arrive = 0u;
            __threadfence();
            *(volatile unsigned*)&g_gen = gen + 1u;
        } else {
            while (*(volatile unsigned*)&g_gen == gen) { __nanosleep(64); }
        }
    }
    __syncthreads();
}

// ---------------- shared memory union ----------------
struct SmemU {
    union {
        float patch[CIN*PATCH*PATCH];                       // conv
        struct { float As[16][68];  float Bs[16][68];  } g; // 64x64 tile
        struct { float As[16][36];  float Bs[16][132]; } h; // 32x128 tile
        struct { float As[16][36];  float Bs[16][68];  } w; // 32x64 tile
        struct {
            unsigned long long qcb[NCHUNK];
            unsigned long long kbv[NTOK];
            unsigned long long vbv[NTOK];
            unsigned char at[NCHUNK][NTOK];
        } a;                                                // attn
    };
};

// ---------------- epilogue (shared by all tiles) ----------------
// MODE 0: LIF -> spike   MODE 1: yout += acc   MODE 2: LIF -> yout += spike
template<int MODE>
__device__ __forceinline__ void ep_one(int m, int n, int N, float vv,
        const float* __restrict__ scale, const float* __restrict__ bias,
        float* __restrict__ mem, float* __restrict__ spk, float* __restrict__ yout)
{
    size_t idx = (size_t)m*N + n;
    if (MODE == 1) {
        yout[idx] = __fadd_rn(yout[idx], vv);
    } else {
        vv = __fadd_rn(__fmul_rn(vv, scale[n]), bias[n]);
        float mm = __fadd_rn(__fmul_rn(BETAF, mem[idx]), vv);
        float s = (mm > 1.0f) ? 1.0f : 0.0f;
        mem[idx] = __fadd_rn(mm, -s);
        if (MODE == 0) spk[idx] = s;
        else           yout[idx] = __fadd_rn(yout[idx], s);
    }
}

// ---------------- gemm 64x64 tile, 4x4 micro (QKV) ----------------
template<int MODE>
__device__ __forceinline__ void gemm_t64(SmemU* sm,
        const float* __restrict__ A, const float* __restrict__ W,
        int N, int K, int bm, int bn,
        const float* __restrict__ scale, const float* __restrict__ bias,
        float* __restrict__ mem, float* __restrict__ spk, float* __restrict__ yout)
{
    const int tid = threadIdx.x;
    const int tx = tid & 15;
    const int ty = tid >> 4;
    const int lr = tid >> 2;         // 0..63
    const int lk = (tid & 3) << 2;   // 0,4,8,12

    float acc[4][4];
    #pragma unroll
    for (int i = 0; i < 4; i++)
        #pragma unroll
        for (int j = 0; j < 4; j++) acc[i][j] = 0.f;

    for (int k0 = 0; k0 < K; k0 += 16) {
        float4 av = make_float4(0.f,0.f,0.f,0.f);
        int ar = bm + lr;
        if (ar < ROWS) av = *reinterpret_cast<const float4*>(A + (size_t)ar*K + k0 + lk);
        sm->g.As[lk+0][lr] = av.x; sm->g.As[lk+1][lr] = av.y;
        sm->g.As[lk+2][lr] = av.z; sm->g.As[lk+3][lr] = av.w;
        float4 bv = *reinterpret_cast<const float4*>(W + (size_t)(bn+lr)*K + k0 + lk);
        sm->g.Bs[lk+0][lr] = bv.x; sm->g.Bs[lk+1][lr] = bv.y;
        sm->g.Bs[lk+2][lr] = bv.z; sm->g.Bs[lk+3][lr] = bv.w;
        __syncthreads();
        #pragma unroll
        for (int kk = 0; kk < 16; kk++) {   // strictly ascending k
            float4 a = *reinterpret_cast<const float4*>(&sm->g.As[kk][ty*4]);
            float4 b = *reinterpret_cast<const float4*>(&sm->g.Bs[kk][tx*4]);
            acc[0][0]=__fmaf_rn(a.x,b.x,acc[0][0]); acc[0][1]=__fmaf_rn(a.x,b.y,acc[0][1]);
            acc[0][2]=__fmaf_rn(a.x,b.z,acc[0][2]); acc[0][3]=__fmaf_rn(a.x,b.w,acc[0][3]);
            acc[1][0]=__fmaf_rn(a.y,b.x,acc[1][0]); acc[1][1]=__fmaf_rn(a.y,b.y,acc[1][1]);
            acc[1][2]=__fmaf_rn(a.y,b.z,acc[1][2]); acc[1][3]=__fmaf_rn(a.y,b.w,acc[1][3]);
            acc[2][0]=__fmaf_rn(a.z,b.x,acc[2][0]); acc[2][1]=__fmaf_rn(a.z,b.y,acc[2][1]);
            acc[2][2]=__fmaf_rn(a.z,b.z,acc[2][2]); acc[2][3]=__fmaf_rn(a.z,b.w,acc[2][3]);
            acc[3][0]=__fmaf_rn(a.w,b.x,acc[3][0]); acc[3][1]=__fmaf_rn(a.w,b.y,acc[3][1]);
            acc[3][2]=__fmaf_rn(a.w,b.z,acc[3][2]); acc[3][3]=__fmaf_rn(a.w,b.w,acc[3][3]);
        }
        __syncthreads();
    }
    #pragma unroll
    for (int i = 0; i < 4; i++) {
        int m = bm + ty*4 + i;
        if (m >= ROWS) break;
        #pragma unroll
        for (int j = 0; j < 4; j++)
            ep_one<MODE>(m, bn + tx*4 + j, N, acc[i][j], scale, bias, mem, spk, yout);
    }
}

// ---------------- gemm 32x128 tile, 4x4 micro (MLP1) ----------------
template<int MODE>
__device__ __forceinline__ void gemm_t32x128(SmemU* sm,
        const float* __restrict__ A, const float* __restrict__ W,
        int N, int K, int bm, int bn,
        const float* __restrict__ scale, const float* __restrict__ bias,
        float* __restrict__ mem, float* __restrict__ spk, float* __restrict__ yout)
{
    const int tid = threadIdx.x;
    const int tx = tid & 31;   // cols tx*4 (0..127)
    const int ty = tid >> 5;   // rows ty*4 (0..31)

    float acc[4][4];
    #pragma unroll
    for (int i = 0; i < 4; i++)
        #pragma unroll
        for (int j = 0; j < 4; j++) acc[i][j] = 0.f;

    for (int k0 = 0; k0 < K; k0 += 16) {
        if (tid < 128) {
            int row = tid >> 2, kq = (tid & 3) << 2;
            int ar = bm + row;
            float4 av = make_float4(0.f,0.f,0.f,0.f);
            if (ar < ROWS) av = *reinterpret_cast<const float4*>(A + (size_t)ar*K + k0 + kq);
            sm->h.As[kq+0][row]=av.x; sm->h.As[kq+1][row]=av.y;
            sm->h.As[kq+2][row]=av.z; sm->h.As[kq+3][row]=av.w;
        }
        #pragma unroll
        for (int e = tid; e < 512; e += 256) {
            int n = e >> 2, kq = (e & 3) << 2;
            float4 bv = *reinterpret_cast<const float4*>(W + (size_t)(bn+n)*K + k0 + kq);
            sm->h.Bs[kq+0][n]=bv.x; sm->h.Bs[kq+1][n]=bv.y;
            sm->h.Bs[kq+2][n]=bv.z; sm->h.Bs[kq+3][n]=bv.w;
        }
        __syncthreads();
        #pragma unroll
        for (int kk = 0; kk < 16; kk++) {
            float a0 = sm->h.As[kk][ty*4+0];
            float a1 = sm->h.As[kk][ty*4+1];
            float a2 = sm->h.As[kk][ty*4+2];
            float a3 = sm->h.As[kk][ty*4+3];
            float4 b = *reinterpret_cast<const float4*>(&sm->h.Bs[kk][tx*4]);
            acc[0][0]=__fmaf_rn(a0,b.x,acc[0][0]); acc[0][1]=__fmaf_rn(a0,b.y,acc[0][1]);
            acc[0][2]=__fmaf_rn(a0,b.z,acc[0][2]); acc[0][3]=__fmaf_rn(a0,b.w,acc[0][3]);
            acc[1][0]=__fmaf_rn(a1,b.x,acc[1][0]); acc[1][1]=__fmaf_rn(a1,b.y,acc[1][1]);
            acc[1][2]=__fmaf_rn(a1,b.z,acc[1][2]); acc[1][3]=__fmaf_rn(a1,b.w,acc[1][3]);
            acc[2][0]=__fmaf_rn(a2,b.x,acc[2][0]); acc[2][1]=__fmaf_rn(a2,b.y,acc[2][1]);
            acc[2][2]=__fmaf_rn(a2,b.z,acc[2][2]); acc[2][3]=__fmaf_rn(a2,b.w,acc[2][3]);
            acc[3][0]=__fmaf_rn(a3,b.x,acc[3][0]); acc[3][1]=__fmaf_rn(a3,b.y,acc[3][1]);
            acc[3][2]=__fmaf_rn(a3,b.z,acc[3][2]); acc[3][3]=__fmaf_rn(a3,b.w,acc[3][3]);
        }
        __syncthreads();
    }
    #pragma unroll
    for (int i = 0; i < 4; i++) {
        int m = bm + ty*4 + i;
        if (m >= ROWS) break;
        #pragma unroll
        for (int j = 0; j < 4; j++)
            ep_one<MODE>(m, bn + tx*4 + j, N, acc[i][j], scale, bias, mem, spk, yout);
    }
}

// ---------------- gemm 32x64 tile, 2x4 micro (Wo, MLP2) ----------------
template<int MODE>
__device__ __forceinline__ void gemm_t32x64(SmemU* sm,
        const float* __restrict__ A, const float* __restrict__ W,
        int N, int K, int bm, int bn,
        const float* __restrict__ scale, const float* __restrict__ bias,
        float* __restrict__ mem, float* __restrict__ spk, float* __restrict__ yout)
{
    const int tid = threadIdx.x;
    const int tx = tid & 15;   // cols tx*4 (0..63)
    const int ty = tid >> 4;   // rows ty*2 (0..31)

    float acc[2][4];
    #pragma unroll
    for (int i = 0; i < 2; i++)
        #pragma unroll
        for (int j = 0; j < 4; j++) acc[i][j] = 0.f;

    for (int k0 = 0; k0 < K; k0 += 16) {
        if (tid < 128) {
            int row = tid >> 2, kq = (tid & 3) << 2;
            int ar = bm + row;
            float4 av = make_float4(0.f,0.f,0.f,0.f);
            if (ar < ROWS) av = *reinterpret_cast<const float4*>(A + (size_t)ar*K + k0 + kq);
            sm->w.As[kq+0][row]=av.x; sm->w.As[kq+1][row]=av.y;
            sm->w.As[kq+2][row]=av.z; sm->w.As[kq+3][row]=av.w;
        }
        {
            int n = tid >> 2, kq = (tid & 3) << 2;
            float4 bv = *reinterpret_cast<const float4*>(W + (size_t)(bn+n)*K + k0 + kq);
            sm->w.Bs[kq+0][n]=bv.x; sm->w.Bs[kq+1][n]=bv.y;
            sm->w.Bs[kq+2][n]=bv.z; sm->w.Bs[kq+3][n]=bv.w;
        }
        __syncthreads();
        #pragma unroll
        for (int kk = 0; kk < 16; kk++) {
            float a0 = sm->w.As[kk][ty*2+0];
            float a1 = sm->w.As[kk][ty*2+1];
            float4 b = *reinterpret_cast<const float4*>(&sm->w.Bs[kk][tx*4]);
            acc[0][0]=__fmaf_rn(a0,b.x,acc[0][0]); acc[0][1]=__fmaf_rn(a0,b.y,acc[0][1]);
            acc[0][2]=__fmaf_rn(a0,b.z,acc[0][2]); acc[0][3]=__fmaf_rn(a0,b.w,acc[0][3]);
            acc[1][0]=__fmaf_rn(a1,b.x,acc[1][0]); acc[1][1]=__fmaf_rn(a1,b.y,acc[1][1]);
            acc[1][2]=__fmaf_rn(a1,b.z,acc[1][2]); acc[1][3]=__fmaf_rn(a1,b.w,acc[1][3]);
        }
        __syncthreads();
    }
    #pragma unroll
    for (int i = 0; i < 2; i++) {
        int m = bm + ty*2 + i;
        if (m >= ROWS) break;
        #pragma unroll
        for (int j = 0; j < 4; j++)
            ep_one<MODE>(m, bn + tx*4 + j, N, acc[i][j], scale, bias, mem, spk, yout);
    }
}

// ---------------- layernorm row, XLA:CPU vectorized-reduce order ----------------
__device__ __forceinline__ void ln_row_warp(const float* __restrict__ rin,
        const float* __restrict__ g, const float* __restrict__ bta, float* __restrict__ out)
{
    const unsigned fm = 0xffffffffu;
    int lane = threadIdx.x & 31;
    float a = 0.f;
    if (lane < 4) {
        for (int t2 = 0; t2 < 96; t2++) a = __fadd_rn(a, rin[4*t2 + lane]);
    }
    float a0 = __shfl_sync(fm, a, 0), a1 = __shfl_sync(fm, a, 1);
    float a2 = __shfl_sync(fm, a, 2), a3 = __shfl_sync(fm, a, 3);
    float mean = __fdiv_rn(__fadd_rn(__fadd_rn(a0, a2), __fadd_rn(a1, a3)), 384.0f);

    float b = 0.f;
    if (lane < 4) {
        for (int t2 = 0; t2 < 96; t2++) {
            float d = __fadd_rn(rin[4*t2 + lane], -mean);
            b = __fadd_rn(b, __fmul_rn(d, d));
        }
    }
    float b0 = __shfl_sync(fm, b, 0), b1 = __shfl_sync(fm, b, 1);
    float b2 = __shfl_sync(fm, b, 2), b3 = __shfl_sync(fm, b, 3);
    float var = __fdiv_rn(__fadd_rn(__fadd_rn(b0, b2), __fadd_rn(b1, b3)), 384.0f);
    float inv = __fdiv_rn(1.0f, __fsqrt_rn(__fadd_rn(var, EPSF)));

    for (int d = lane; d < DMODEL; d += 32) {
        float dv = __fadd_rn(rin[d], -mean);
        out[d] = __fadd_rn(__fmul_rn(__fmul_rn(dv, inv), g[d]), bta[d]);
    }
}

// ---------------- zero helper ----------------
__device__ __forceinline__ void zero_arr(float* p, int n, int gtid, int nth)
{
    for (int i = gtid; i < n; i += nth) p[i] = 0.f;
}

// ---------------- the megakernel ----------------
__global__ void __launch_bounds__(256, 2) mega(
    const float* __restrict__ x,      const float* __restrict__ conv_w,
    const float* __restrict__ bn0_s,  const float* __restrict__ bn0_b,
    const float* __restrict__ pos,
    const float* __restrict__ Wq,     const float* __restrict__ bnq_s, const float* __restrict__ bnq_b,
    const float* __restrict__ Wk,     const float* __restrict__ bnk_s, const float* __restrict__ bnk_b,
    const float* __restrict__ Wv,     const float* __restrict__ bnv_s, const float* __restrict__ bnv_b,
    const float* __restrict__ Wo,
    const float* __restrict__ ln1_g,  const float* __restrict__ ln1_b,
    const float* __restrict__ W1,     const float* __restrict__ bn1_s, const float* __restrict__ bn1_b,
    const float* __restrict__ W2,     const float* __restrict__ bn2_s, const float* __restrict__ bn2_b,
    const float* __restrict__ ln2_g,  const float* __restrict__ ln2_b,
    const float* __restrict__ lnf_g,  const float* __restrict__ lnf_b,
    const float* __restrict__ head_w, const float* __restrict__ head_b,
    float* __restrict__ out)
{
    __shared__ SmemU sm;
    const int nb  = gridDim.x;
    const int tid = threadIdx.x;
    const int wrp = tid >> 5;
    const int gtid = blockIdx.x * 256 + tid;
    const int nth  = nb * 256;

    // ---- zero persistent state ----
    zero_arr(g_mpe, ROWS*DMODEL, gtid, nth);
    zero_arr(g_mq,  DEPTH*ROWS*DMODEL, gtid, nth);
    zero_arr(g_mk,  DEPTH*ROWS*DMODEL, gtid, nth);
    zero_arr(g_mv,  DEPTH*ROWS*DMODEL, gtid, nth);
    zero_arr(g_m1,  DEPTH*ROWS*MLPD, gtid, nth);
    zero_arr(g_m2,  DEPTH*ROWS*DMODEL, gtid, nth);
    zero_arr(g_mh,  BSZ*NCLS, gtid, nth);
    zero_arr(g_acc, BSZ*NCLS, gtid, nth);

    // ---- conv patch embed (timestep-invariant); Eigen tap order (kh, kw, c), c minor ----
    for (int item = blockIdx.x; item < ROWS; item += nb) {
        int b = item / NTOK, n = item % NTOK;
        int py = n / HP, px = n % HP;
        for (int idx = tid; idx < 768; idx += 256) {
            int c = idx >> 8; int rem = idx & 255; int i = rem >> 4; int j = rem & 15;
            sm.patch[idx] = x[(((size_t)b*CIN + c)*IMG + (py*PATCH + i))*IMG + (px*PATCH + j)];
        }
        __syncthreads();
        for (int d = tid; d < DMODEL; d += 256) {
            const float* wr = conv_w + (size_t)d*768;
            float acc = 0.f;
            for (int i = 0; i < PATCH; i++)
                for (int j = 0; j < PATCH; j++)
                    #pragma unroll
                    for (int c = 0; c < CIN; c++) {
                        int off = c*256 + i*16 + j;
                        acc = __fmaf_rn(sm.patch[off], wr[off], acc);
                    }
            g_h[((size_t)b*NTOK + n)*DMODEL + d] = __fadd_rn(__fmul_rn(acc, bn0_s[d]), bn0_b[d]);
        }
        __syncthreads();
    }
    gsync();

    // ---- timestep loop ----
    for (int t = 0; t < TSTEPS; t++) {
        // patch-embed LIF + pos
        for (int i = gtid; i < ROWS*DMODEL; i += nth) {
            float mm = __fadd_rn(__fmul_rn(BETAF, g_mpe[i]), g_h[i]);
            float s = (mm > 1.0f) ? 1.0f : 0.0f;
            g_mpe[i] = __fadd_rn(mm, -s);
            g_y[i] = __fadd_rn(s, pos[i % (NTOK*DMODEL)]);
        }
        gsync();

        for (int l = 0; l < DEPTH; l++) {
            const size_t wOff  = (size_t)l * DMODEL * DMODEL;
            const size_t w1Off = (size_t)l * MLPD * DMODEL;
            const size_t memD  = (size_t)l * ROWS * DMODEL;
            const size_t memM  = (size_t)l * ROWS * MLPD;
            const float* Wq_l = Wq + wOff;   const float* Wk_l = Wk + wOff;
            const float* Wv_l = Wv + wOff;   const float* Wo_l = Wo + wOff;
            const float* W1_l = W1 + w1Off;  const float* W2_l = W2 + w1Off;
            const float* qs = bnq_s + l*DMODEL, *qb2 = bnq_b + l*DMODEL;
            const float* ks = bnk_s + l*DMODEL, *kb2 = bnk_b + l*DMODEL;
            const float* vs = bnv_s + l*DMODEL, *vb2 = bnv_b + l*DMODEL;
            const float* m1s = bn1_s + l*MLPD,  *m1b = bn1_b + l*MLPD;
            const float* m2s = bn2_s + l*DMODEL, *m2b = bn2_b + l*DMODEL;

            // LN1 (warp per row)
            for (int row = blockIdx.x*8 + wrp; row < ROWS; row += nb*8)
                ln_row_warp(g_y + (size_t)row*DMODEL, ln1_g + l*DMODEL, ln1_b + l*DMODEL,
                            g_xn + (size_t)row*DMODEL);
            gsync();

            // QKV: 3 x 78 = 234 tiles of 64x64
            for (int t5 = blockIdx.x; t5 < 234; t5 += nb) {
                int which = t5 / 78, s = t5 % 78;
                int bm = (s / 6) * 64, bn = (s % 6) * 64;
                if (which == 0)
                    gemm_t64<0>(&sm, g_xn, Wq_l, DMODEL, DMODEL, bm, bn, qs, qb2, g_mq + memD, g_q, 0);
                else if (which == 1)
                    gemm_t64<0>(&sm, g_xn, Wk_l, DMODEL, DMODEL, bm, bn, ks, kb2, g_mk + memD, g_k, 0);
                else
                    gemm_t64<0>(&sm, g_xn, Wv_l, DMODEL, DMODEL, bm, bn, vs, vb2, g_mv + memD, g_v, 0);
            }
            gsync();

            // attention: exact integer counts + rounded serial-m einsum2
            for (int item = blockIdx.x; item < 7*32; item += nb) {
                int chunk = item % 7;
                int bh = item / 7;
                int b = bh >> 3, h = bh & 7;
                int n0 = chunk * NCHUNK;
                __syncthreads();
                for (int tt = tid; tt < NTOK*2 + NCHUNK; tt += 256) {
                    int which, n;
                    if (tt < NTOK)        { which = 1; n = tt; }
                    else if (tt < 2*NTOK) { which = 2; n = tt - NTOK; }
                    else                  { which = 0; n = n0 + (tt - 2*NTOK); }
                    const float* src = (which == 0 ? g_q : (which == 1 ? g_k : g_v))
                                       + ((size_t)(b*NTOK + n))*DMODEL + h*HD;
                    unsigned long long bits = 0ull;
                    #pragma unroll
                    for (int j = 0; j < HD; j++)
                        if (src[j] != 0.f) bits |= (1ull << j);
                    if (which == 0)      sm.a.qcb[n - n0] = bits;
                    else if (which == 1) sm.a.kbv[n] = bits;
                    else                 sm.a.vbv[n] = bits;
                }
                __syncthreads();
                for (int idx = tid; idx < NCHUNK*NTOK; idx += 256)
                    sm.a.at[idx/NTOK][idx%NTOK] =
                        (unsigned char)__popcll(sm.a.qcb[idx/NTOK] & sm.a.kbv[idx%NTOK]);
                __syncthreads();
                for (int it2 = tid; it2 < NCHUNK*HD; it2 += 256) {
                    int n = it2 / HD, d = it2 % HD;
                    const unsigned char* arow = sm.a.at[n];
                    float acc = 0.f;
                    for (int m = 0; m < NTOK; m++) {
                        float a = __fmul_rn((float)arow[m], SCALEF);
                        float vm = (float)((sm.a.vbv[m] >> d) & 1ull);
                        acc = __fmaf_rn(a, vm, acc);
                    }
                    g_o[((size_t)(b*NTOK + n0 + n))*DMODEL + h*HD + d] = acc;
                }
                __syncthreads();
            }
            gsync();

            // Wo residual: 25x6 = 150 tiles of 32x64
            for (int t5 = blockIdx.x; t5 < 150; t5 += nb) {
                int bm = (t5 / 6) * 32, bn = (t5 % 6) * 64;
                gemm_t32x64<1>(&sm, g_o, Wo_l, DMODEL, DMODEL, bm, bn, 0, 0, 0, 0, g_y);
            }
            gsync();

            // LN2
            for (int row = blockIdx.x*8 + wrp; row < ROWS; row += nb*8)
                ln_row_warp(g_y + (size_t)row*DMODEL, ln2_g + l*DMODEL, ln2_b + l*DMODEL,
                            g_xn + (size_t)row*DMODEL);
            gsync();

            // MLP1: 25x12 = 300 tiles of 32x128
            for (int t5 = blockIdx.x; t5 < 300; t5 += nb) {
                int bm = (t5 / 12) * 32, bn = (t5 % 12) * 128;
                gemm_t32x128<0>(&sm, g_xn, W1_l, MLPD, DMODEL, bm, bn, m1s, m1b, g_m1 + memM, g_s1, 0);
            }
            gsync();

            // MLP2: 25x6 = 150 tiles of 32x64, K=1536
            for (int t5 = blockIdx.x; t5 < 150; t5 += nb) {
                int bm = (t5 / 6) * 32, bn = (t5 % 6) * 64;
                gemm_t32x64<2>(&sm, g_s1, W2_l, DMODEL, MLPD, bm, bn, m2s, m2b, g_m2 + memD, 0, g_y);
            }
            gsync();
        }

        // final LN
        for (int row = blockIdx.x*8 + wrp; row < ROWS; row += nb*8)
            ln_row_warp(g_y + (size_t)row*DMODEL, lnf_g, lnf_b, g_xn + (size_t)row*DMODEL);
        gsync();

        // token-mean pool (serial over n, ascending — major-dim reduce order)
        for (int it = gtid; it < BSZ*DMODEL; it += nth) {
            int b = it / DMODEL, d = it % DMODEL;
            float acc = 0.f;
            for (int n = 0; n < NTOK; n++)
                acc = __fadd_rn(acc, g_xn[((size_t)(b*NTOK + n))*DMODEL + d]);
            g_pool[it] = __fdiv_rn(acc, 196.0f);
        }
        gsync();

        // head logits + LIF (block 0): Eigen serial-k FMA
        if (blockIdx.x == 0 && tid < BSZ*NCLS) {
            int b = tid / NCLS, c = tid % NCLS;
            float acc = 0.f;
            for (int d = 0; d < DMODEL; d++)
                acc = __fmaf_rn(g_pool[b*DMODEL + d], head_w[d*NCLS + c], acc);
            float inp = __fadd_rn(acc, head_b[c]);
            float mm = __fadd_rn(__fmul_rn(BETAF, g_mh[tid]), inp);
            float s = (mm > 1.0f) ? 1.0f : 0.0f;
            g_mh[tid] = __fadd_rn(mm, -s);
            g_acc[tid] += s;
        }
        gsync();
    }

    if (blockIdx.x == 0 && tid < BSZ*NCLS)
        out[tid] = __fdiv_rn(g_acc[tid], (float)TSTEPS);
}

// ---------------- host ----------------
extern "C" void kernel_launch(void* const* d_in, const int* in_sizes, int n_in,
                              void* d_out, int out_size)
{
    const float* x       = (const float*)d_in[0];
    const float* conv_w  = (const float*)d_in[1];
    const float* bn0_s   = (const float*)d_in[2];
    const float* bn0_b   = (const float*)d_in[3];
    const float* pos     = (const float*)d_in[4];
    const float* Wq      = (const float*)d_in[5];
    const float* bnq_s   = (const float*)d_in[6];
    const float* bnq_b   = (const float*)d_in[7];
    const float* Wk      = (const float*)d_in[8];
    const float* bnk_s   = (const float*)d_in[9];
    const float* bnk_b   = (const float*)d_in[10];
    const float* Wv      = (const float*)d_in[11];
    const float* bnv_s   = (const float*)d_in[12];
    const float* bnv_b   = (const float*)d_in[13];
    const float* Wo      = (const float*)d_in[14];
    const float* ln1_g   = (const float*)d_in[15];
    const float* ln1_b   = (const float*)d_in[16];
    const float* W1      = (const float*)d_in[17];
    const float* bn1_s   = (const float*)d_in[18];
    const float* bn1_b   = (const float*)d_in[19];
    const float* W2      = (const float*)d_in[20];
    const float* bn2_s   = (const float*)d_in[21];
    const float* bn2_b   = (const float*)d_in[22];
    const float* ln2_g   = (const float*)d_in[23];
    const float* ln2_b   = (const float*)d_in[24];
    const float* lnf_g   = (const float*)d_in[25];
    const float* lnf_b   = (const float*)d_in[26];
    const float* head_w  = (const float*)d_in[27];
    const float* head_b  = (const float*)d_in[28];
    float* out = (float*)d_out;

    int dev = 0;
    cudaGetDevice(&dev);
    int nsm = 0;
    cudaDeviceGetAttribute(&nsm, cudaDevAttrMultiProcessorCount, dev);
    int bpm = 0;
    cudaOccupancyMaxActiveBlocksPerMultiprocessor(&bpm, mega, 256, 0);
    if (bpm < 1) bpm = 1;
    if (bpm > 2) bpm = 2;
    int nblk = nsm * bpm;

    mega<<<nblk, 256>>>(x, conv_w, bn0_s, bn0_b, pos,
                        Wq, bnq_s, bnq_b, Wk, bnk_s, bnk_b, Wv, bnv_s, bnv_b, Wo,
                        ln1_g, ln1_b, W1, bn1_s, bn1_b, W2, bn2_s, bn2_b,
                        ln2_g, ln2_b, lnf_g, lnf_b, head_w, head_b, out);
}

// round 10
// speedup vs baseline: 1.0607x; 1.0583x over previous
#include <cuda_runtime.h>
#include <math.h>
#include <stdint.h>

// ---------------- problem constants ----------------
#define BSZ    4
#define CIN    3
#define IMG    224
#define PATCH  16
#define DMODEL 384
#define DEPTH  4
#define NHEAD  8
#define HD     48
#define MLPD   1536
#define NCLS   5
#define TSTEPS 25
#define NTOK   196
#define ROWS   (BSZ*NTOK) // 784
#define HP     14
#define BETAF  0.9f
#define EPSF   1e-5f
#define SCALEF 0.14433756729740643f  // 48^-0.5
#define NCHUNK 28                     // 196 = 7*28

// ---------------- device state ----------------
__device__ float g_h   [ROWS*DMODEL];
__device__ float g_y   [ROWS*DMODEL];
__device__ float g_xn  [ROWS*DMODEL];
__device__ float g_q   [ROWS*DMODEL];
__device__ float g_k   [ROWS*DMODEL];
__device__ float g_v   [ROWS*DMODEL];
__device__ float g_o   [ROWS*DMODEL];
__device__ float g_s1  [ROWS*MLPD];
__device__ float g_pool[BSZ*DMODEL];
__device__ float g_mpe [ROWS*DMODEL];
__device__ float g_mq  [DEPTH*ROWS*DMODEL];
__device__ float g_mk  [DEPTH*ROWS*DMODEL];
__device__ float g_mv  [DEPTH*ROWS*DMODEL];
__device__ float g_m1  [DEPTH*ROWS*MLPD];
__device__ float g_m2  [DEPTH*ROWS*DMODEL];
__device__ float g_mh  [BSZ*NCLS];
__device__ float g_acc [BSZ*NCLS];

// software grid barrier state
__device__ unsigned g_arrive;
__device__ unsigned g_gen;

__device__ __forceinline__ void gsync()
{
    __syncthreads();
    if (threadIdx.x == 0) {
        __threadfence();
        unsigned gen = *(volatile unsigned*)&g_gen;
        unsigned nb = gridDim.x;
        if (atomicAdd(&g_arrive, 1u) == nb - 1u) {
            g_arrive = 0u;
            __threadfence();
            *(volatile unsigned*)&g_gen = gen + 1u;
        } else {
            while (*(volatile unsigned*)&g_gen == gen) { __nanosleep(64); }
        }
    }
    __syncthreads();
}

// ---------------- shared memory union (double-buffered gemm tiles) ----------------
struct SmemU {
    union {
        float patch[CIN*PATCH*PATCH];                              // conv
        struct { float As[2][16][68];  float Bs[2][16][68];  } g;  // 64x64  (17.4 KB)
        struct { float As[2][16][36];  float Bs[2][16][132]; } h;  // 32x128 (21.5 KB)
        struct { float As[2][16][36];  float Bs[2][16][68];  } w;  // 32x64  (13.3 KB)
        struct {
            unsigned long long qcb[NCHUNK];
            unsigned long long kbv[NTOK];
            unsigned long long vbv[NTOK];
            unsigned char at[NCHUNK][NTOK];
        } a;                                                       // attn
    };
};

// ---------------- epilogue ----------------
// MODE 0: LIF -> spike   MODE 1: yout += acc   MODE 2: LIF -> yout += spike
template<int MODE>
__device__ __forceinline__ void ep_one(int m, int n, int N, float vv,
        const float* __restrict__ scale, const float* __restrict__ bias,
        float* __restrict__ mem, float* __restrict__ spk, float* __restrict__ yout)
{
    size_t idx = (size_t)m*N + n;
    if (MODE == 1) {
        yout[idx] = __fadd_rn(yout[idx], vv);
    } else {
        vv = __fadd_rn(__fmul_rn(vv, scale[n]), bias[n]);
        float mm = __fadd_rn(__fmul_rn(BETAF, mem[idx]), vv);
        float s = (mm > 1.0f) ? 1.0f : 0.0f;
        mem[idx] = __fadd_rn(mm, -s);
        if (MODE == 0) spk[idx] = s;
        else           yout[idx] = __fadd_rn(yout[idx], s);
    }
}

// ---------------- gemm 64x64 tile, 4x4 micro, reg-prefetch pipelined (QKV) ----------------
template<int MODE>
__device__ __forceinline__ void gemm_t64(SmemU* sm,
        const float* __restrict__ A, const float* __restrict__ W,
        int N, int K, int bm, int bn,
        const float* __restrict__ scale, const float* __restrict__ bias,
        float* __restrict__ mem, float* __restrict__ spk, float* __restrict__ yout)
{
    const int tid = threadIdx.x;
    const int tx = tid & 15;
    const int ty = tid >> 4;
    const int lr = tid >> 2;         // 0..63
    const int lk = (tid & 3) << 2;   // 0,4,8,12
    const int ar = bm + lr;
    const bool aok = (ar < ROWS);
    const float* aptr = A + (size_t)(aok ? ar : 0)*K + lk;
    const float* bptr = W + (size_t)(bn + lr)*K + lk;

    float acc[4][4];
    #pragma unroll
    for (int i = 0; i < 4; i++)
        #pragma unroll
        for (int j = 0; j < 4; j++) acc[i][j] = 0.f;

    const int nch = K >> 4;
    float4 av = aok ? *reinterpret_cast<const float4*>(aptr) : make_float4(0.f,0.f,0.f,0.f);
    float4 bv = *reinterpret_cast<const float4*>(bptr);
    sm->g.As[0][lk+0][lr]=av.x; sm->g.As[0][lk+1][lr]=av.y;
    sm->g.As[0][lk+2][lr]=av.z; sm->g.As[0][lk+3][lr]=av.w;
    sm->g.Bs[0][lk+0][lr]=bv.x; sm->g.Bs[0][lk+1][lr]=bv.y;
    sm->g.Bs[0][lk+2][lr]=bv.z; sm->g.Bs[0][lk+3][lr]=bv.w;
    __syncthreads();

    for (int c = 0; c < nch; c++) {
        const int buf = c & 1;
        float4 av2, bv2;
        const bool more = (c + 1 < nch);
        if (more) {
            av2 = aok ? *reinterpret_cast<const float4*>(aptr + (c+1)*16)
                      : make_float4(0.f,0.f,0.f,0.f);
            bv2 = *reinterpret_cast<const float4*>(bptr + (c+1)*16);
        }
        #pragma unroll
        for (int kk = 0; kk < 16; kk++) {   // strictly ascending k
            float4 a = *reinterpret_cast<const float4*>(&sm->g.As[buf][kk][ty*4]);
            float4 b = *reinterpret_cast<const float4*>(&sm->g.Bs[buf][kk][tx*4]);
            acc[0][0]=__fmaf_rn(a.x,b.x,acc[0][0]); acc[0][1]=__fmaf_rn(a.x,b.y,acc[0][1]);
            acc[0][2]=__fmaf_rn(a.x,b.z,acc[0][2]); acc[0][3]=__fmaf_rn(a.x,b.w,acc[0][3]);
            acc[1][0]=__fmaf_rn(a.y,b.x,acc[1][0]); acc[1][1]=__fmaf_rn(a.y,b.y,acc[1][1]);
            acc[1][2]=__fmaf_rn(a.y,b.z,acc[1][2]); acc[1][3]=__fmaf_rn(a.y,b.w,acc[1][3]);
            acc[2][0]=__fmaf_rn(a.z,b.x,acc[2][0]); acc[2][1]=__fmaf_rn(a.z,b.y,acc[2][1]);
            acc[2][2]=__fmaf_rn(a.z,b.z,acc[2][2]); acc[2][3]=__fmaf_rn(a.z,b.w,acc[2][3]);
            acc[3][0]=__fmaf_rn(a.w,b.x,acc[3][0]); acc[3][1]=__fmaf_rn(a.w,b.y,acc[3][1]);
            acc[3][2]=__fmaf_rn(a.w,b.z,acc[3][2]); acc[3][3]=__fmaf_rn(a.w,b.w,acc[3][3]);
        }
        if (more) {
            const int nbuf = buf ^ 1;
            sm->g.As[nbuf][lk+0][lr]=av2.x; sm->g.As[nbuf][lk+1][lr]=av2.y;
            sm->g.As[nbuf][lk+2][lr]=av2.z; sm->g.As[nbuf][lk+3][lr]=av2.w;
            sm->g.Bs[nbuf][lk+0][lr]=bv2.x; sm->g.Bs[nbuf][lk+1][lr]=bv2.y;
            sm->g.Bs[nbuf][lk+2][lr]=bv2.z; sm->g.Bs[nbuf][lk+3][lr]=bv2.w;
        }
        __syncthreads();
    }
    #pragma unroll
    for (int i = 0; i < 4; i++) {
        int m = bm + ty*4 + i;
        if (m >= ROWS) break;
        #pragma unroll
        for (int j = 0; j < 4; j++)
            ep_one<MODE>(m, bn + tx*4 + j, N, acc[i][j], scale, bias, mem, spk, yout);
    }
}

// ---------------- gemm 32x128 tile, 4x4 micro, pipelined (MLP1) ----------------
template<int MODE>
__device__ __forceinline__ void gemm_t32x128(SmemU* sm,
        const float* __restrict__ A, const float* __restrict__ W,
        int N, int K, int bm, int bn,
        const float* __restrict__ scale, const float* __restrict__ bias,
        float* __restrict__ mem, float* __restrict__ spk, float* __restrict__ yout)
{
    const int tid = threadIdx.x;
    const int tx = tid & 31;   // cols tx*4 (0..127)
    const int ty = tid >> 5;   // rows ty*4 (0..31)
    const int lrow = tid >> 2;          // A row (tid<128), B n-low
    const int lkq  = (tid & 3) << 2;
    const bool aload = (tid < 128);
    const int ar = bm + lrow;
    const bool aok = aload && (ar < ROWS);
    const float* aptr = A + (size_t)(aok ? ar : 0)*K + lkq;
    const float* bptr0 = W + (size_t)(bn + lrow)*K + lkq;        // n = 0..63
    const float* bptr1 = W + (size_t)(bn + 64 + lrow)*K + lkq;   // n = 64..127

    float acc[4][4];
    #pragma unroll
    for (int i = 0; i < 4; i++)
        #pragma unroll
        for (int j = 0; j < 4; j++) acc[i][j] = 0.f;

    const int nch = K >> 4;
    float4 av = aok ? *reinterpret_cast<const float4*>(aptr) : make_float4(0.f,0.f,0.f,0.f);
    float4 bva = *reinterpret_cast<const float4*>(bptr0);
    float4 bvb = *reinterpret_cast<const float4*>(bptr1);
    if (aload) {
        sm->h.As[0][lkq+0][lrow]=av.x; sm->h.As[0][lkq+1][lrow]=av.y;
        sm->h.As[0][lkq+2][lrow]=av.z; sm->h.As[0][lkq+3][lrow]=av.w;
    }
    sm->h.Bs[0][lkq+0][lrow]=bva.x;    sm->h.Bs[0][lkq+1][lrow]=bva.y;
    sm->h.Bs[0][lkq+2][lrow]=bva.z;    sm->h.Bs[0][lkq+3][lrow]=bva.w;
    sm->h.Bs[0][lkq+0][64+lrow]=bvb.x; sm->h.Bs[0][lkq+1][64+lrow]=bvb.y;
    sm->h.Bs[0][lkq+2][64+lrow]=bvb.z; sm->h.Bs[0][lkq+3][64+lrow]=bvb.w;
    __syncthreads();

    for (int c = 0; c < nch; c++) {
        const int buf = c & 1;
        float4 av2, b2a, b2b;
        const bool more = (c + 1 < nch);
        if (more) {
            av2 = aok ? *reinterpret_cast<const float4*>(aptr + (c+1)*16)
                      : make_float4(0.f,0.f,0.f,0.f);
            b2a = *reinterpret_cast<const float4*>(bptr0 + (c+1)*16);
            b2b = *reinterpret_cast<const float4*>(bptr1 + (c+1)*16);
        }
        #pragma unroll
        for (int kk = 0; kk < 16; kk++) {
            float a0 = sm->h.As[buf][kk][ty*4+0];
            float a1 = sm->h.As[buf][kk][ty*4+1];
            float a2 = sm->h.As[buf][kk][ty*4+2];
            float a3 = sm->h.As[buf][kk][ty*4+3];
            float4 b = *reinterpret_cast<const float4*>(&sm->h.Bs[buf][kk][tx*4]);
            acc[0][0]=__fmaf_rn(a0,b.x,acc[0][0]); acc[0][1]=__fmaf_rn(a0,b.y,acc[0][1]);
            acc[0][2]=__fmaf_rn(a0,b.z,acc[0][2]); acc[0][3]=__fmaf_rn(a0,b.w,acc[0][3]);
            acc[1][0]=__fmaf_rn(a1,b.x,acc[1][0]); acc[1][1]=__fmaf_rn(a1,b.y,acc[1][1]);
            acc[1][2]=__fmaf_rn(a1,b.z,acc[1][2]); acc[1][3]=__fmaf_rn(a1,b.w,acc[1][3]);
            acc[2][0]=__fmaf_rn(a2,b.x,acc[2][0]); acc[2][1]=__fmaf_rn(a2,b.y,acc[2][1]);
            acc[2][2]=__fmaf_rn(a2,b.z,acc[2][2]); acc[2][3]=__fmaf_rn(a2,b.w,acc[2][3]);
            acc[3][0]=__fmaf_rn(a3,b.x,acc[3][0]); acc[3][1]=__fmaf_rn(a3,b.y,acc[3][1]);
            acc[3][2]=__fmaf_rn(a3,b.z,acc[3][2]); acc[3][3]=__fmaf_rn(a3,b.w,acc[3][3]);
        }
        if (more) {
            const int nbuf = buf ^ 1;
            if (aload) {
                sm->h.As[nbuf][lkq+0][lrow]=av2.x; sm->h.As[nbuf][lkq+1][lrow]=av2.y;
                sm->h.As[nbuf][lkq+2][lrow]=av2.z; sm->h.As[nbuf][lkq+3][lrow]=av2.w;
            }
            sm->h.Bs[nbuf][lkq+0][lrow]=b2a.x;    sm->h.Bs[nbuf][lkq+1][lrow]=b2a.y;
            sm->h.Bs[nbuf][lkq+2][lrow]=b2a.z;    sm->h.Bs[nbuf][lkq+3][lrow]=b2a.w;
            sm->h.Bs[nbuf][lkq+0][64+lrow]=b2b.x; sm->h.Bs[nbuf][lkq+1][64+lrow]=b2b.y;
            sm->h.Bs[nbuf][lkq+2][64+lrow]=b2b.z; sm->h.Bs[nbuf][lkq+3][64+lrow]=b2b.w;
        }
        __syncthreads();
    }
    #pragma unroll
    for (int i = 0; i < 4; i++) {
        int m = bm + ty*4 + i;
        if (m >= ROWS) break;
        #pragma unroll
        for (int j = 0; j < 4; j++)
            ep_one<MODE>(m, bn + tx*4 + j, N, acc[i][j], scale, bias, mem, spk, yout);
    }
}

// ---------------- gemm 32x64 tile, 2x4 micro, pipelined (Wo, MLP2) ----------------
template<int MODE>
__device__ __forceinline__ void gemm_t32x64(SmemU* sm,
        const float* __restrict__ A, const float* __restrict__ W,
        int N, int K, int bm, int bn,
        const float* __restrict__ scale, const float* __restrict__ bias,
        float* __restrict__ mem, float* __restrict__ spk, float* __restrict__ yout)
{
    const int tid = threadIdx.x;
    const int tx = tid & 15;   // cols tx*4 (0..63)
    const int ty = tid >> 4;   // rows ty*2 (0..31)
    const int lrow = tid >> 2;          // A row (tid<128), B n
    const int lkq  = (tid & 3) << 2;
    const bool aload = (tid < 128);
    const int ar = bm + lrow;
    const bool aok = aload && (ar < ROWS);
    const float* aptr = A + (size_t)(aok ? ar : 0)*K + lkq;
    const float* bptr = W + (size_t)(bn + lrow)*K + lkq;

    float acc[2][4];
    #pragma unroll
    for (int i = 0; i < 2; i++)
        #pragma unroll
        for (int j = 0; j < 4; j++) acc[i][j] = 0.f;

    const int nch = K >> 4;
    float4 av = aok ? *reinterpret_cast<const float4*>(aptr) : make_float4(0.f,0.f,0.f,0.f);
    float4 bv = *reinterpret_cast<const float4*>(bptr);
    if (aload) {
        sm->w.As[0][lkq+0][lrow]=av.x; sm->w.As[0][lkq+1][lrow]=av.y;
        sm->w.As[0][lkq+2][lrow]=av.z; sm->w.As[0][lkq+3][lrow]=av.w;
    }
    sm->w.Bs[0][lkq+0][lrow]=bv.x; sm->w.Bs[0][lkq+1][lrow]=bv.y;
    sm->w.Bs[0][lkq+2][lrow]=bv.z; sm->w.Bs[0][lkq+3][lrow]=bv.w;
    __syncthreads();

    for (int c = 0; c < nch; c++) {
        const int buf = c & 1;
        float4 av2, bv2;
        const bool more = (c + 1 < nch);
        if (more) {
            av2 = aok ? *reinterpret_cast<const float4*>(aptr + (c+1)*16)
                      : make_float4(0.f,0.f,0.f,0.f);
            bv2 = *reinterpret_cast<const float4*>(bptr + (c+1)*16);
        }
        #pragma unroll
        for (int kk = 0; kk < 16; kk++) {
            float a0 = sm->w.As[buf][kk][ty*2+0];
            float a1 = sm->w.As[buf][kk][ty*2+1];
            float4 b = *reinterpret_cast<const float4*>(&sm->w.Bs[buf][kk][tx*4]);
            acc[0][0]=__fmaf_rn(a0,b.x,acc[0][0]); acc[0][1]=__fmaf_rn(a0,b.y,acc[0][1]);
            acc[0][2]=__fmaf_rn(a0,b.z,acc[0][2]); acc[0][3]=__fmaf_rn(a0,b.w,acc[0][3]);
            acc[1][0]=__fmaf_rn(a1,b.x,acc[1][0]); acc[1][1]=__fmaf_rn(a1,b.y,acc[1][1]);
            acc[1][2]=__fmaf_rn(a1,b.z,acc[1][2]); acc[1][3]=__fmaf_rn(a1,b.w,acc[1][3]);
        }
        if (more) {
            const int nbuf = buf ^ 1;
            if (aload) {
                sm->w.As[nbuf][lkq+0][lrow]=av2.x; sm->w.As[nbuf][lkq+1][lrow]=av2.y;
                sm->w.As[nbuf][lkq+2][lrow]=av2.z; sm->w.As[nbuf][lkq+3][lrow]=av2.w;
            }
            sm->w.Bs[nbuf][lkq+0][lrow]=bv2.x; sm->w.Bs[nbuf][lkq+1][lrow]=bv2.y;
            sm->w.Bs[nbuf][lkq+2][lrow]=bv2.z; sm->w.Bs[nbuf][lkq+3][lrow]=bv2.w;
        }
        __syncthreads();
    }
    #pragma unroll
    for (int i = 0; i < 2; i++) {
        int m = bm + ty*2 + i;
        if (m >= ROWS) break;
        #pragma unroll
        for (int j = 0; j < 4; j++)
            ep_one<MODE>(m, bn + tx*4 + j, N, acc[i][j], scale, bias, mem, spk, yout);
    }
}

// ---------------- layernorm row, XLA:CPU vectorized-reduce order ----------------
__device__ __forceinline__ void ln_row_warp(const float* __restrict__ rin,
        const float* __restrict__ g, const float* __restrict__ bta, float* __restrict__ out)
{
    const unsigned fm = 0xffffffffu;
    int lane = threadIdx.x & 31;
    float a = 0.f;
    if (lane < 4) {
        for (int t2 = 0; t2 < 96; t2++) a = __fadd_rn(a, rin[4*t2 + lane]);
    }
    float a0 = __shfl_sync(fm, a, 0), a1 = __shfl_sync(fm, a, 1);
    float a2 = __shfl_sync(fm, a, 2), a3 = __shfl_sync(fm, a, 3);
    float mean = __fdiv_rn(__fadd_rn(__fadd_rn(a0, a2), __fadd_rn(a1, a3)), 384.0f);

    float b = 0.f;
    if (lane < 4) {
        for (int t2 = 0; t2 < 96; t2++) {
            float d = __fadd_rn(rin[4*t2 + lane], -mean);
            b = __fadd_rn(b, __fmul_rn(d, d));
        }
    }
    float b0 = __shfl_sync(fm, b, 0), b1 = __shfl_sync(fm, b, 1);
    float b2 = __shfl_sync(fm, b, 2), b3 = __shfl_sync(fm, b, 3);
    float var = __fdiv_rn(__fadd_rn(__fadd_rn(b0, b2), __fadd_rn(b1, b3)), 384.0f);
    float inv = __fdiv_rn(1.0f, __fsqrt_rn(__fadd_rn(var, EPSF)));

    for (int d = lane; d < DMODEL; d += 32) {
        float dv = __fadd_rn(rin[d], -mean);
        out[d] = __fadd_rn(__fmul_rn(__fmul_rn(dv, inv), g[d]), bta[d]);
    }
}

// ---------------- zero helper ----------------
__device__ __forceinline__ void zero_arr(float* p, int n, int gtid, int nth)
{
    for (int i = gtid; i < n; i += nth) p[i] = 0.f;
}

// ---------------- the megakernel ----------------
__global__ void __launch_bounds__(256, 2) mega(
    const float* __restrict__ x,      const float* __restrict__ conv_w,
    const float* __restrict__ bn0_s,  const float* __restrict__ bn0_b,
    const float* __restrict__ pos,
    const float* __restrict__ Wq,     const float* __restrict__ bnq_s, const float* __restrict__ bnq_b,
    const float* __restrict__ Wk,     const float* __restrict__ bnk_s, const float* __restrict__ bnk_b,
    const float* __restrict__ Wv,     const float* __restrict__ bnv_s, const float* __restrict__ bnv_b,
    const float* __restrict__ Wo,
    const float* __restrict__ ln1_g,  const float* __restrict__ ln1_b,
    const float* __restrict__ W1,     const float* __restrict__ bn1_s, const float* __restrict__ bn1_b,
    const float* __restrict__ W2,     const float* __restrict__ bn2_s, const float* __restrict__ bn2_b,
    const float* __restrict__ ln2_g,  const float* __restrict__ ln2_b,
    const float* __restrict__ lnf_g,  const float* __restrict__ lnf_b,
    const float* __restrict__ head_w, const float* __restrict__ head_b,
    float* __restrict__ out)
{
    __shared__ SmemU sm;
    const int nb  = gridDim.x;
    const int tid = threadIdx.x;
    const int wrp = tid >> 5;
    const int gtid = blockIdx.x * 256 + tid;
    const int nth  = nb * 256;

    // ---- zero persistent state ----
    zero_arr(g_mpe, ROWS*DMODEL, gtid, nth);
    zero_arr(g_mq,  DEPTH*ROWS*DMODEL, gtid, nth);
    zero_arr(g_mk,  DEPTH*ROWS*DMODEL, gtid, nth);
    zero_arr(g_mv,  DEPTH*ROWS*DMODEL, gtid, nth);
    zero_arr(g_m1,  DEPTH*ROWS*MLPD, gtid, nth);
    zero_arr(g_m2,  DEPTH*ROWS*DMODEL, gtid, nth);
    zero_arr(g_mh,  BSZ*NCLS, gtid, nth);
    zero_arr(g_acc, BSZ*NCLS, gtid, nth);

    // ---- conv patch embed (timestep-invariant); Eigen tap order (kh, kw, c), c minor ----
    for (int item = blockIdx.x; item < ROWS; item += nb) {
        int b = item / NTOK, n = item % NTOK;
        int py = n / HP, px = n % HP;
        for (int idx = tid; idx < 768; idx += 256) {
            int c = idx >> 8; int rem = idx & 255; int i = rem >> 4; int j = rem & 15;
            sm.patch[idx] = x[(((size_t)b*CIN + c)*IMG + (py*PATCH + i))*IMG + (px*PATCH + j)];
        }
        __syncthreads();
        for (int d = tid; d < DMODEL; d += 256) {
            const float* wr = conv_w + (size_t)d*768;
            float acc = 0.f;
            for (int i = 0; i < PATCH; i++)
                for (int j = 0; j < PATCH; j++)
                    #pragma unroll
                    for (int c = 0; c < CIN; c++) {
                        int off = c*256 + i*16 + j;
                        acc = __fmaf_rn(sm.patch[off], wr[off], acc);
                    }
            g_h[((size_t)b*NTOK + n)*DMODEL + d] = __fadd_rn(__fmul_rn(acc, bn0_s[d]), bn0_b[d]);
        }
        __syncthreads();
    }
    gsync();

    // ---- timestep loop ----
    for (int t = 0; t < TSTEPS; t++) {
        // patch-embed LIF + pos
        for (int i = gtid; i < ROWS*DMODEL; i += nth) {
            float mm = __fadd_rn(__fmul_rn(BETAF, g_mpe[i]), g_h[i]);
            float s = (mm > 1.0f) ? 1.0f : 0.0f;
            g_mpe[i] = __fadd_rn(mm, -s);
            g_y[i] = __fadd_rn(s, pos[i % (NTOK*DMODEL)]);
        }
        gsync();

        for (int l = 0; l < DEPTH; l++) {
            const size_t wOff  = (size_t)l * DMODEL * DMODEL;
            const size_t w1Off = (size_t)l * MLPD * DMODEL;
            const size_t memD  = (size_t)l * ROWS * DMODEL;
            const size_t memM  = (size_t)l * ROWS * MLPD;
            const float* Wq_l = Wq + wOff;   const float* Wk_l = Wk + wOff;
            const float* Wv_l = Wv + wOff;   const float* Wo_l = Wo + wOff;
            const float* W1_l = W1 + w1Off;  const float* W2_l = W2 + w1Off;
            const float* qs = bnq_s + l*DMODEL, *qb2 = bnq_b + l*DMODEL;
            const float* ks = bnk_s + l*DMODEL, *kb2 = bnk_b + l*DMODEL;
            const float* vs = bnv_s + l*DMODEL, *vb2 = bnv_b + l*DMODEL;
            const float* m1s = bn1_s + l*MLPD,  *m1b = bn1_b + l*MLPD;
            const float* m2s = bn2_s + l*DMODEL, *m2b = bn2_b + l*DMODEL;

            // LN1 (warp per row)
            for (int row = blockIdx.x*8 + wrp; row < ROWS; row += nb*8)
                ln_row_warp(g_y + (size_t)row*DMODEL, ln1_g + l*DMODEL, ln1_b + l*DMODEL,
                            g_xn + (size_t)row*DMODEL);
            gsync();

            // QKV: 3 x 78 = 234 tiles of 64x64
            for (int t5 = blockIdx.x; t5 < 234; t5 += nb) {
                int which = t5 / 78, s = t5 % 78;
                int bm = (s / 6) * 64, bn = (s % 6) * 64;
                if (which == 0)
                    gemm_t64<0>(&sm, g_xn, Wq_l, DMODEL, DMODEL, bm, bn, qs, qb2, g_mq + memD, g_q, 0);
                else if (which == 1)
                    gemm_t64<0>(&sm, g_xn, Wk_l, DMODEL, DMODEL, bm, bn, ks, kb2, g_mk + memD, g_k, 0);
                else
                    gemm_t64<0>(&sm, g_xn, Wv_l, DMODEL, DMODEL, bm, bn, vs, vb2, g_mv + memD, g_v, 0);
            }
            gsync();

            // attention: exact integer counts + rounded serial-m einsum2 (batched chains)
            for (int item = blockIdx.x; item < 7*32; item += nb) {
                int chunk = item % 7;
                int bh = item / 7;
                int b = bh >> 3, h = bh & 7;
                int n0 = chunk * NCHUNK;
                __syncthreads();
                for (int tt = tid; tt < NTOK*2 + NCHUNK; tt += 256) {
                    int which, n;
                    if (tt < NTOK)        { which = 1; n = tt; }
                    else if (tt < 2*NTOK) { which = 2; n = tt - NTOK; }
                    else                  { which = 0; n = n0 + (tt - 2*NTOK); }
                    const float* src = (which == 0 ? g_q : (which == 1 ? g_k : g_v))
                                       + ((size_t)(b*NTOK + n))*DMODEL + h*HD;
                    unsigned long long bits = 0ull;
                    #pragma unroll
                    for (int j = 0; j < HD; j++)
                        if (src[j] != 0.f) bits |= (1ull << j);
                    if (which == 0)      sm.a.qcb[n - n0] = bits;
                    else if (which == 1) sm.a.kbv[n] = bits;
                    else                 sm.a.vbv[n] = bits;
                }
                __syncthreads();
                for (int idx = tid; idx < NCHUNK*NTOK; idx += 256)
                    sm.a.at[idx/NTOK][idx%NTOK] =
                        (unsigned char)__popcll(sm.a.qcb[idx/NTOK] & sm.a.kbv[idx%NTOK]);
                __syncthreads();
                // batched einsum2: each thread's <=6 outputs share one m-loop,
                // each output keeps its own serial-m FMA chain (bit-exact)
                {
                    float accv[6];
                    const unsigned char* ar6[6];
                    int dd6[6];
                    int cnt = 0;
                    for (int it2 = tid; it2 < NCHUNK*HD; it2 += 256) {
                        ar6[cnt] = sm.a.at[it2 / HD];
                        dd6[cnt] = it2 % HD;
                        accv[cnt] = 0.f;
                        cnt++;
                    }
                    for (int m = 0; m < NTOK; m++) {
                        unsigned long long vb = sm.a.vbv[m];
                        #pragma unroll
                        for (int i = 0; i < 6; i++) {
                            if (i < cnt) {
                                float a = __fmul_rn((float)ar6[i][m], SCALEF);
                                float vm = (float)((vb >> dd6[i]) & 1ull);
                                accv[i] = __fmaf_rn(a, vm, accv[i]);
                            }
                        }
                    }
                    int ci = 0;
                    for (int it2 = tid; it2 < NCHUNK*HD; it2 += 256) {
                        int n = it2 / HD, d = it2 % HD;
                        g_o[((size_t)(b*NTOK + n0 + n))*DMODEL + h*HD + d] = accv[ci++];
                    }
                }
                __syncthreads();
            }
            gsync();

            // Wo residual: 25x6 = 150 tiles of 32x64
            for (int t5 = blockIdx.x; t5 < 150; t5 += nb) {
                int bm = (t5 / 6) * 32, bn = (t5 % 6) * 64;
                gemm_t32x64<1>(&sm, g_o, Wo_l, DMODEL, DMODEL, bm, bn, 0, 0, 0, 0, g_y);
            }
            gsync();

            // LN2
            for (int row = blockIdx.x*8 + wrp; row < ROWS; row += nb*8)
                ln_row_warp(g_y + (size_t)row*DMODEL, ln2_g + l*DMODEL, ln2_b + l*DMODEL,
                            g_xn + (size_t)row*DMODEL);
            gsync();

            // MLP1: 25x12 = 300 tiles of 32x128
            for (int t5 = blockIdx.x; t5 < 300; t5 += nb) {
                int bm = (t5 / 12) * 32, bn = (t5 % 12) * 128;
                gemm_t32x128<0>(&sm, g_xn, W1_l, MLPD, DMODEL, bm, bn, m1s, m1b, g_m1 + memM, g_s1, 0);
            }
            gsync();

            // MLP2: 25x6 = 150 tiles of 32x64, K=1536
            for (int t5 = blockIdx.x; t5 < 150; t5 += nb) {
                int bm = (t5 / 6) * 32, bn = (t5 % 6) * 64;
                gemm_t32x64<2>(&sm, g_s1, W2_l, DMODEL, MLPD, bm, bn, m2s, m2b, g_m2 + memD, 0, g_y);
            }
            gsync();
        }

        // final LN
        for (int row = blockIdx.x*8 + wrp; row < ROWS; row += nb*8)
            ln_row_warp(g_y + (size_t)row*DMODEL, lnf_g, lnf_b, g_xn + (size_t)row*DMODEL);
        gsync();

        // token-mean pool (serial over n, ascending — major-dim reduce order)
        for (int it = gtid; it < BSZ*DMODEL; it += nth) {
            int b = it / DMODEL, d = it % DMODEL;
            float acc = 0.f;
            for (int n = 0; n < NTOK; n++)
                acc = __fadd_rn(acc, g_xn[((size_t)(b*NTOK + n))*DMODEL + d]);
            g_pool[it] = __fdiv_rn(acc, 196.0f);
        }
        gsync();

        // head logits + LIF (block 0): Eigen serial-k FMA
        if (blockIdx.x == 0 && tid < BSZ*NCLS) {
            int b = tid / NCLS, c = tid % NCLS;
            float acc = 0.f;
            for (int d = 0; d < DMODEL; d++)
                acc = __fmaf_rn(g_pool[b*DMODEL + d], head_w[d*NCLS + c], acc);
            float inp = __fadd_rn(acc, head_b[c]);
            float mm = __fadd_rn(__fmul_rn(BETAF, g_mh[tid]), inp);
            float s = (mm > 1.0f) ? 1.0f : 0.0f;
            g_mh[tid] = __fadd_rn(mm, -s);
            g_acc[tid] += s;
        }
        gsync();
    }

    if (blockIdx.x == 0 && tid < BSZ*NCLS)
        out[tid] = __fdiv_rn(g_acc[tid], (float)TSTEPS);
}

// ---------------- host ----------------
extern "C" void kernel_launch(void* const* d_in, const int* in_sizes, int n_in,
                              void* d_out, int out_size)
{
    const float* x       = (const float*)d_in[0];
    const float* conv_w  = (const float*)d_in[1];
    const float* bn0_s   = (const float*)d_in[2];
    const float* bn0_b   = (const float*)d_in[3];
    const float* pos     = (const float*)d_in[4];
    const float* Wq      = (const float*)d_in[5];
    const float* bnq_s   = (const float*)d_in[6];
    const float* bnq_b   = (const float*)d_in[7];
    const float* Wk      = (const float*)d_in[8];
    const float* bnk_s   = (const float*)d_in[9];
    const float* bnk_b   = (const float*)d_in[10];
    const float* Wv      = (const float*)d_in[11];
    const float* bnv_s   = (const float*)d_in[12];
    const float* bnv_b   = (const float*)d_in[13];
    const float* Wo      = (const float*)d_in[14];
    const float* ln1_g   = (const float*)d_in[15];
    const float* ln1_b   = (const float*)d_in[16];
    const float* W1      = (const float*)d_in[17];
    const float* bn1_s   = (const float*)d_in[18];
    const float* bn1_b   = (const float*)d_in[19];
    const float* W2      = (const float*)d_in[20];
    const float* bn2_s   = (const float*)d_in[21];
    const float* bn2_b   = (const float*)d_in[22];
    const float* ln2_g   = (const float*)d_in[23];
    const float* ln2_b   = (const float*)d_in[24];
    const float* lnf_g   = (const float*)d_in[25];
    const float* lnf_b   = (const float*)d_in[26];
    const float* head_w  = (const float*)d_in[27];
    const float* head_b  = (const float*)d_in[28];
    float* out = (float*)d_out;

    int dev = 0;
    cudaGetDevice(&dev);
    int nsm = 0;
    cudaDeviceGetAttribute(&nsm, cudaDevAttrMultiProcessorCount, dev);
    int bpm = 0;
    cudaOccupancyMaxActiveBlocksPerMultiprocessor(&bpm, mega, 256, 0);
    if (bpm < 1) bpm = 1;
    if (bpm > 2) bpm = 2;
    int nblk = nsm * bpm;

    mega<<<nblk, 256>>>(x, conv_w, bn0_s, bn0_b, pos,
                        Wq, bnq_s, bnq_b, Wk, bnk_s, bnk_b, Wv, bnv_s, bnv_b, Wo,
                        ln1_g, ln1_b, W1, bn1_s, bn1_b, W2, bn2_s, bn2_b,
                        ln2_g, ln2_b, lnf_g, lnf_b, head_w, head_b, out);
}

// round 11
// speedup vs baseline: 1.4838x; 1.3989x over previous
#include <cuda_runtime.h>
#include <math.h>
#include <stdint.h>

// ---------------- problem constants ----------------
#define BSZ    4
#define CIN    3
#define IMG    224
#define PATCH  16
#define DMODEL 384
#define DEPTH  4
#define NHEAD  8
#define HD     48
#define MLPD   1536
#define NCLS   5
#define TSTEPS 25
#define NTOK   196
#define ROWS   (BSZ*NTOK) // 784
#define HP     14
#define BETAF  0.9f
#define EPSF   1e-5f
#define SCALEF 0.14433756729740643f  // 48^-0.5
#define NCHUNK 28                     // 196 = 7*28

// ---------------- device state ----------------
__device__ float g_h   [ROWS*DMODEL];
__device__ float g_y   [ROWS*DMODEL];
__device__ float g_xn  [ROWS*DMODEL];
__device__ float g_q   [ROWS*DMODEL];
__device__ float g_k   [ROWS*DMODEL];
__device__ float g_v   [ROWS*DMODEL];
__device__ float g_o   [ROWS*DMODEL];
__device__ float g_s1  [ROWS*MLPD];
__device__ float g_pool[BSZ*DMODEL];
__device__ float g_mpe [ROWS*DMODEL];
__device__ float g_mq  [DEPTH*ROWS*DMODEL];
__device__ float g_mk  [DEPTH*ROWS*DMODEL];
__device__ float g_mv  [DEPTH*ROWS*DMODEL];
__device__ float g_m1  [DEPTH*ROWS*MLPD];
__device__ float g_m2  [DEPTH*ROWS*DMODEL];
__device__ float g_mh  [BSZ*NCLS];
__device__ float g_acc [BSZ*NCLS];

// software grid barrier state
__device__ unsigned g_arrive;
__device__ unsigned g_gen;

__device__ __forceinline__ void gsync()
{
    __syncthreads();
    if (threadIdx.x == 0) {
        __threadfence();
        unsigned gen = *(volatile unsigned*)&g_gen;
        unsigned nb = gridDim.x;
        if (atomicAdd(&g_arrive, 1u) == nb - 1u) {
            g_arrive = 0u;
            __threadfence();
            *(volatile unsigned*)&g_gen = gen + 1u;
        } else {
            while (*(volatile unsigned*)&g_gen == gen) { __nanosleep(64); }
        }
    }
    __syncthreads();
}

// ---------------- shared memory union ----------------
struct SmemU {
    union {
        float patch[CIN*PATCH*PATCH];                              // conv
        struct { float As[2][16][68];  float Bs[2][16][68];  } g;  // 64x64
        struct { float As[2][16][36];  float Bs[2][16][132]; } h;  // 32x128
        struct { float As[2][16][17];  float Bs[2][16][68];  } w2; // 16x64
        struct {
            unsigned long long qcb[NCHUNK];
            unsigned long long kbv[NTOK];
            unsigned long long vbv[NTOK];
            float af[NCHUNK][197];                                 // fl(count*SCALE)
        } a;                                                       // attn ~25.4KB
    };
};

// ---------------- epilogue ----------------
// MODE 0: LIF -> spike   MODE 1: yout += acc   MODE 2: LIF -> yout += spike
template<int MODE>
__device__ __forceinline__ void ep_one(int m, int n, int N, float vv,
        const float* __restrict__ scale, const float* __restrict__ bias,
        float* __restrict__ mem, float* __restrict__ spk, float* __restrict__ yout)
{
    size_t idx = (size_t)m*N + n;
    if (MODE == 1) {
        yout[idx] = __fadd_rn(yout[idx], vv);
    } else {
        vv = __fadd_rn(__fmul_rn(vv, scale[n]), bias[n]);
        float mm = __fadd_rn(__fmul_rn(BETAF, mem[idx]), vv);
        float s = (mm > 1.0f) ? 1.0f : 0.0f;
        mem[idx] = __fadd_rn(mm, -s);
        if (MODE == 0) spk[idx] = s;
        else           yout[idx] = __fadd_rn(yout[idx], s);
    }
}

// ---------------- gemm 64x64 tile, 4x4 micro, reg-prefetch pipelined (QKV) ----------------
template<int MODE>
__device__ __forceinline__ void gemm_t64(SmemU* sm,
        const float* __restrict__ A, const float* __restrict__ W,
        int N, int K, int bm, int bn,
        const float* __restrict__ scale, const float* __restrict__ bias,
        float* __restrict__ mem, float* __restrict__ spk, float* __restrict__ yout)
{
    const int tid = threadIdx.x;
    const int tx = tid & 15;
    const int ty = tid >> 4;
    const int lr = tid >> 2;         // 0..63
    const int lk = (tid & 3) << 2;   // 0,4,8,12
    const int ar = bm + lr;
    const bool aok = (ar < ROWS);
    const float* aptr = A + (size_t)(aok ? ar : 0)*K + lk;
    const float* bptr = W + (size_t)(bn + lr)*K + lk;

    float acc[4][4];
    #pragma unroll
    for (int i = 0; i < 4; i++)
        #pragma unroll
        for (int j = 0; j < 4; j++) acc[i][j] = 0.f;

    const int nch = K >> 4;
    float4 av = aok ? *reinterpret_cast<const float4*>(aptr) : make_float4(0.f,0.f,0.f,0.f);
    float4 bv = *reinterpret_cast<const float4*>(bptr);
    sm->g.As[0][lk+0][lr]=av.x; sm->g.As[0][lk+1][lr]=av.y;
    sm->g.As[0][lk+2][lr]=av.z; sm->g.As[0][lk+3][lr]=av.w;
    sm->g.Bs[0][lk+0][lr]=bv.x; sm->g.Bs[0][lk+1][lr]=bv.y;
    sm->g.Bs[0][lk+2][lr]=bv.z; sm->g.Bs[0][lk+3][lr]=bv.w;
    __syncthreads();

    for (int c = 0; c < nch; c++) {
        const int buf = c & 1;
        float4 av2, bv2;
        const bool more = (c + 1 < nch);
        if (more) {
            av2 = aok ? *reinterpret_cast<const float4*>(aptr + (c+1)*16)
                      : make_float4(0.f,0.f,0.f,0.f);
            bv2 = *reinterpret_cast<const float4*>(bptr + (c+1)*16);
        }
        #pragma unroll
        for (int kk = 0; kk < 16; kk++) {   // strictly ascending k
            float4 a = *reinterpret_cast<const float4*>(&sm->g.As[buf][kk][ty*4]);
            float4 b = *reinterpret_cast<const float4*>(&sm->g.Bs[buf][kk][tx*4]);
            acc[0][0]=__fmaf_rn(a.x,b.x,acc[0][0]); acc[0][1]=__fmaf_rn(a.x,b.y,acc[0][1]);
            acc[0][2]=__fmaf_rn(a.x,b.z,acc[0][2]); acc[0][3]=__fmaf_rn(a.x,b.w,acc[0][3]);
            acc[1][0]=__fmaf_rn(a.y,b.x,acc[1][0]); acc[1][1]=__fmaf_rn(a.y,b.y,acc[1][1]);
            acc[1][2]=__fmaf_rn(a.y,b.z,acc[1][2]); acc[1][3]=__fmaf_rn(a.y,b.w,acc[1][3]);
            acc[2][0]=__fmaf_rn(a.z,b.x,acc[2][0]); acc[2][1]=__fmaf_rn(a.z,b.y,acc[2][1]);
            acc[2][2]=__fmaf_rn(a.z,b.z,acc[2][2]); acc[2][3]=__fmaf_rn(a.z,b.w,acc[2][3]);
            acc[3][0]=__fmaf_rn(a.w,b.x,acc[3][0]); acc[3][1]=__fmaf_rn(a.w,b.y,acc[3][1]);
            acc[3][2]=__fmaf_rn(a.w,b.z,acc[3][2]); acc[3][3]=__fmaf_rn(a.w,b.w,acc[3][3]);
        }
        if (more) {
            const int nbuf = buf ^ 1;
            sm->g.As[nbuf][lk+0][lr]=av2.x; sm->g.As[nbuf][lk+1][lr]=av2.y;
            sm->g.As[nbuf][lk+2][lr]=av2.z; sm->g.As[nbuf][lk+3][lr]=av2.w;
            sm->g.Bs[nbuf][lk+0][lr]=bv2.x; sm->g.Bs[nbuf][lk+1][lr]=bv2.y;
            sm->g.Bs[nbuf][lk+2][lr]=bv2.z; sm->g.Bs[nbuf][lk+3][lr]=bv2.w;
        }
        __syncthreads();
    }
    #pragma unroll
    for (int i = 0; i < 4; i++) {
        int m = bm + ty*4 + i;
        if (m >= ROWS) break;
        #pragma unroll
        for (int j = 0; j < 4; j++)
            ep_one<MODE>(m, bn + tx*4 + j, N, acc[i][j], scale, bias, mem, spk, yout);
    }
}

// ---------------- gemm 32x128 tile, 4x4 micro, pipelined (MLP1) ----------------
template<int MODE>
__device__ __forceinline__ void gemm_t32x128(SmemU* sm,
        const float* __restrict__ A, const float* __restrict__ W,
        int N, int K, int bm, int bn,
        const float* __restrict__ scale, const float* __restrict__ bias,
        float* __restrict__ mem, float* __restrict__ spk, float* __restrict__ yout)
{
    const int tid = threadIdx.x;
    const int tx = tid & 31;   // cols tx*4 (0..127)
    const int ty = tid >> 5;   // rows ty*4 (0..31)
    const int lrow = tid >> 2;
    const int lkq  = (tid & 3) << 2;
    const bool aload = (tid < 128);
    const int ar = bm + lrow;
    const bool aok = aload && (ar < ROWS);
    const float* aptr = A + (size_t)(aok ? ar : 0)*K + lkq;
    const float* bptr0 = W + (size_t)(bn + lrow)*K + lkq;
    const float* bptr1 = W + (size_t)(bn + 64 + lrow)*K + lkq;

    float acc[4][4];
    #pragma unroll
    for (int i = 0; i < 4; i++)
        #pragma unroll
        for (int j = 0; j < 4; j++) acc[i][j] = 0.f;

    const int nch = K >> 4;
    float4 av = aok ? *reinterpret_cast<const float4*>(aptr) : make_float4(0.f,0.f,0.f,0.f);
    float4 bva = *reinterpret_cast<const float4*>(bptr0);
    float4 bvb = *reinterpret_cast<const float4*>(bptr1);
    if (aload) {
        sm->h.As[0][lkq+0][lrow]=av.x; sm->h.As[0][lkq+1][lrow]=av.y;
        sm->h.As[0][lkq+2][lrow]=av.z; sm->h.As[0][lkq+3][lrow]=av.w;
    }
    sm->h.Bs[0][lkq+0][lrow]=bva.x;    sm->h.Bs[0][lkq+1][lrow]=bva.y;
    sm->h.Bs[0][lkq+2][lrow]=bva.z;    sm->h.Bs[0][lkq+3][lrow]=bva.w;
    sm->h.Bs[0][lkq+0][64+lrow]=bvb.x; sm->h.Bs[0][lkq+1][64+lrow]=bvb.y;
    sm->h.Bs[0][lkq+2][64+lrow]=bvb.z; sm->h.Bs[0][lkq+3][64+lrow]=bvb.w;
    __syncthreads();

    for (int c = 0; c < nch; c++) {
        const int buf = c & 1;
        float4 av2, b2a, b2b;
        const bool more = (c + 1 < nch);
        if (more) {
            av2 = aok ? *reinterpret_cast<const float4*>(aptr + (c+1)*16)
                      : make_float4(0.f,0.f,0.f,0.f);
            b2a = *reinterpret_cast<const float4*>(bptr0 + (c+1)*16);
            b2b = *reinterpret_cast<const float4*>(bptr1 + (c+1)*16);
        }
        #pragma unroll
        for (int kk = 0; kk < 16; kk++) {
            float a0 = sm->h.As[buf][kk][ty*4+0];
            float a1 = sm->h.As[buf][kk][ty*4+1];
            float a2 = sm->h.As[buf][kk][ty*4+2];
            float a3 = sm->h.As[buf][kk][ty*4+3];
            float4 b = *reinterpret_cast<const float4*>(&sm->h.Bs[buf][kk][tx*4]);
            acc[0][0]=__fmaf_rn(a0,b.x,acc[0][0]); acc[0][1]=__fmaf_rn(a0,b.y,acc[0][1]);
            acc[0][2]=__fmaf_rn(a0,b.z,acc[0][2]); acc[0][3]=__fmaf_rn(a0,b.w,acc[0][3]);
            acc[1][0]=__fmaf_rn(a1,b.x,acc[1][0]); acc[1][1]=__fmaf_rn(a1,b.y,acc[1][1]);
            acc[1][2]=__fmaf_rn(a1,b.z,acc[1][2]); acc[1][3]=__fmaf_rn(a1,b.w,acc[1][3]);
            acc[2][0]=__fmaf_rn(a2,b.x,acc[2][0]); acc[2][1]=__fmaf_rn(a2,b.y,acc[2][1]);
            acc[2][2]=__fmaf_rn(a2,b.z,acc[2][2]); acc[2][3]=__fmaf_rn(a2,b.w,acc[2][3]);
            acc[3][0]=__fmaf_rn(a3,b.x,acc[3][0]); acc[3][1]=__fmaf_rn(a3,b.y,acc[3][1]);
            acc[3][2]=__fmaf_rn(a3,b.z,acc[3][2]); acc[3][3]=__fmaf_rn(a3,b.w,acc[3][3]);
        }
        if (more) {
            const int nbuf = buf ^ 1;
            if (aload) {
                sm->h.As[nbuf][lkq+0][lrow]=av2.x; sm->h.As[nbuf][lkq+1][lrow]=av2.y;
                sm->h.As[nbuf][lkq+2][lrow]=av2.z; sm->h.As[nbuf][lkq+3][lrow]=av2.w;
            }
            sm->h.Bs[nbuf][lkq+0][lrow]=b2a.x;    sm->h.Bs[nbuf][lkq+1][lrow]=b2a.y;
            sm->h.Bs[nbuf][lkq+2][lrow]=b2a.z;    sm->h.Bs[nbuf][lkq+3][lrow]=b2a.w;
            sm->h.Bs[nbuf][lkq+0][64+lrow]=b2b.x; sm->h.Bs[nbuf][lkq+1][64+lrow]=b2b.y;
            sm->h.Bs[nbuf][lkq+2][64+lrow]=b2b.z; sm->h.Bs[nbuf][lkq+3][64+lrow]=b2b.w;
        }
        __syncthreads();
    }
    #pragma unroll
    for (int i = 0; i < 4; i++) {
        int m = bm + ty*4 + i;
        if (m >= ROWS) break;
        #pragma unroll
        for (int j = 0; j < 4; j++)
            ep_one<MODE>(m, bn + tx*4 + j, N, acc[i][j], scale, bias, mem, spk, yout);
    }
}

// ---------------- gemm 16x64 tile, 1x4 micro, pipelined (Wo, MLP2; 49x6=294 tiles) ----------------
template<int MODE>
__device__ __forceinline__ void gemm_t16x64(SmemU* sm,
        const float* __restrict__ A, const float* __restrict__ W,
        int N, int K, int bm, int bn,
        const float* __restrict__ scale, const float* __restrict__ bias,
        float* __restrict__ mem, float* __restrict__ spk, float* __restrict__ yout)
{
    const int tid = threadIdx.x;
    const int tx = tid & 15;   // col group
    const int my = tid >> 4;   // row 0..15
    const int lrow = tid >> 2;
    const int lkq  = (tid & 3) << 2;
    const bool aload = (tid < 64);   // 16 rows x 16 k / 4 = 64 float4
    const float* aptr = A + (size_t)(bm + (aload ? lrow : 0))*K + lkq;
    const float* bptr = W + (size_t)(bn + lrow)*K + lkq;

    float acc[4] = {0.f, 0.f, 0.f, 0.f};

    const int nch = K >> 4;
    float4 av, bv;
    if (aload) av = *reinterpret_cast<const float4*>(aptr);
    bv = *reinterpret_cast<const float4*>(bptr);
    if (aload) {
        sm->w2.As[0][lkq+0][lrow]=av.x; sm->w2.As[0][lkq+1][lrow]=av.y;
        sm->w2.As[0][lkq+2][lrow]=av.z; sm->w2.As[0][lkq+3][lrow]=av.w;
    }
    sm->w2.Bs[0][lkq+0][lrow]=bv.x; sm->w2.Bs[0][lkq+1][lrow]=bv.y;
    sm->w2.Bs[0][lkq+2][lrow]=bv.z; sm->w2.Bs[0][lkq+3][lrow]=bv.w;
    __syncthreads();

    for (int c = 0; c < nch; c++) {
        const int buf = c & 1;
        float4 av2, bv2;
        const bool more = (c + 1 < nch);
        if (more) {
            if (aload) av2 = *reinterpret_cast<const float4*>(aptr + (c+1)*16);
            bv2 = *reinterpret_cast<const float4*>(bptr + (c+1)*16);
        }
        #pragma unroll
        for (int kk = 0; kk < 16; kk++) {   // strictly ascending k
            float a = sm->w2.As[buf][kk][my];
            float4 b = *reinterpret_cast<const float4*>(&sm->w2.Bs[buf][kk][tx*4]);
            acc[0]=__fmaf_rn(a,b.x,acc[0]); acc[1]=__fmaf_rn(a,b.y,acc[1]);
            acc[2]=__fmaf_rn(a,b.z,acc[2]); acc[3]=__fmaf_rn(a,b.w,acc[3]);
        }
        if (more) {
            const int nbuf = buf ^ 1;
            if (aload) {
                sm->w2.As[nbuf][lkq+0][lrow]=av2.x; sm->w2.As[nbuf][lkq+1][lrow]=av2.y;
                sm->w2.As[nbuf][lkq+2][lrow]=av2.z; sm->w2.As[nbuf][lkq+3][lrow]=av2.w;
            }
            sm->w2.Bs[nbuf][lkq+0][lrow]=bv2.x; sm->w2.Bs[nbuf][lkq+1][lrow]=bv2.y;
            sm->w2.Bs[nbuf][lkq+2][lrow]=bv2.z; sm->w2.Bs[nbuf][lkq+3][lrow]=bv2.w;
        }
        __syncthreads();
    }
    const int m = bm + my;   // always < ROWS (784 = 49*16)
    #pragma unroll
    for (int j = 0; j < 4; j++)
        ep_one<MODE>(m, bn + tx*4 + j, N, acc[j], scale, bias, mem, spk, yout);
}

// ---------------- layernorm row, XLA:CPU vectorized-reduce order ----------------
__device__ __forceinline__ void ln_row_warp(const float* __restrict__ rin,
        const float* __restrict__ g, const float* __restrict__ bta, float* __restrict__ out)
{
    const unsigned fm = 0xffffffffu;
    int lane = threadIdx.x & 31;
    float a = 0.f;
    if (lane < 4) {
        for (int t2 = 0; t2 < 96; t2++) a = __fadd_rn(a, rin[4*t2 + lane]);
    }
    float a0 = __shfl_sync(fm, a, 0), a1 = __shfl_sync(fm, a, 1);
    float a2 = __shfl_sync(fm, a, 2), a3 = __shfl_sync(fm, a, 3);
    float mean = __fdiv_rn(__fadd_rn(__fadd_rn(a0, a2), __fadd_rn(a1, a3)), 384.0f);

    float b = 0.f;
    if (lane < 4) {
        for (int t2 = 0; t2 < 96; t2++) {
            float d = __fadd_rn(rin[4*t2 + lane], -mean);
            b = __fadd_rn(b, __fmul_rn(d, d));
        }
    }
    float b0 = __shfl_sync(fm, b, 0), b1 = __shfl_sync(fm, b, 1);
    float b2 = __shfl_sync(fm, b, 2), b3 = __shfl_sync(fm, b, 3);
    float var = __fdiv_rn(__fadd_rn(__fadd_rn(b0, b2), __fadd_rn(b1, b3)), 384.0f);
    float inv = __fdiv_rn(1.0f, __fsqrt_rn(__fadd_rn(var, EPSF)));

    for (int d = lane; d < DMODEL; d += 32) {
        float dv = __fadd_rn(rin[d], -mean);
        out[d] = __fadd_rn(__fmul_rn(__fmul_rn(dv, inv), g[d]), bta[d]);
    }
}

// ---------------- patch-embed LIF + pos (strided range) ----------------
__device__ __forceinline__ void patch_lif_range(const float* __restrict__ pos, int start, int stride)
{
    for (int i = start; i < ROWS*DMODEL; i += stride) {
        float mm = __fadd_rn(__fmul_rn(BETAF, g_mpe[i]), g_h[i]);
        float s = (mm > 1.0f) ? 1.0f : 0.0f;
        g_mpe[i] = __fadd_rn(mm, -s);
        g_y[i] = __fadd_rn(s, pos[i % (NTOK*DMODEL)]);
    }
}

// ---------------- zero helper ----------------
__device__ __forceinline__ void zero_arr(float* p, int n, int gtid, int nth)
{
    for (int i = gtid; i < n; i += nth) p[i] = 0.f;
}

// ---------------- the megakernel ----------------
__global__ void __launch_bounds__(256, 2) mega(
    const float* __restrict__ x,      const float* __restrict__ conv_w,
    const float* __restrict__ bn0_s,  const float* __restrict__ bn0_b,
    const float* __restrict__ pos,
    const float* __restrict__ Wq,     const float* __restrict__ bnq_s, const float* __restrict__ bnq_b,
    const float* __restrict__ Wk,     const float* __restrict__ bnk_s, const float* __restrict__ bnk_b,
    const float* __restrict__ Wv,     const float* __restrict__ bnv_s, const float* __restrict__ bnv_b,
    const float* __restrict__ Wo,
    const float* __restrict__ ln1_g,  const float* __restrict__ ln1_b,
    const float* __restrict__ W1,     const float* __restrict__ bn1_s, const float* __restrict__ bn1_b,
    const float* __restrict__ W2,     const float* __restrict__ bn2_s, const float* __restrict__ bn2_b,
    const float* __restrict__ ln2_g,  const float* __restrict__ ln2_b,
    const float* __restrict__ lnf_g,  const float* __restrict__ lnf_b,
    const float* __restrict__ head_w, const float* __restrict__ head_b,
    float* __restrict__ out)
{
    __shared__ SmemU sm;
    const int nb  = gridDim.x;
    const int tid = threadIdx.x;
    const int wrp = tid >> 5;
    const int gtid = blockIdx.x * 256 + tid;
    const int nth  = nb * 256;

    // ---- zero persistent state ----
    zero_arr(g_mpe, ROWS*DMODEL, gtid, nth);
    zero_arr(g_mq,  DEPTH*ROWS*DMODEL, gtid, nth);
    zero_arr(g_mk,  DEPTH*ROWS*DMODEL, gtid, nth);
    zero_arr(g_mv,  DEPTH*ROWS*DMODEL, gtid, nth);
    zero_arr(g_m1,  DEPTH*ROWS*MLPD, gtid, nth);
    zero_arr(g_m2,  DEPTH*ROWS*DMODEL, gtid, nth);
    zero_arr(g_mh,  BSZ*NCLS, gtid, nth);
    zero_arr(g_acc, BSZ*NCLS, gtid, nth);

    // ---- conv patch embed (once); Eigen tap order (kh, kw, c), c minor ----
    for (int item = blockIdx.x; item < ROWS; item += nb) {
        int b = item / NTOK, n = item % NTOK;
        int py = n / HP, px = n % HP;
        for (int idx = tid; idx < 768; idx += 256) {
            int c = idx >> 8; int rem = idx & 255; int i = rem >> 4; int j = rem & 15;
            sm.patch[idx] = x[(((size_t)b*CIN + c)*IMG + (py*PATCH + i))*IMG + (px*PATCH + j)];
        }
        __syncthreads();
        for (int d = tid; d < DMODEL; d += 256) {
            const float* wr = conv_w + (size_t)d*768;
            float acc = 0.f;
            for (int i = 0; i < PATCH; i++)
                for (int j = 0; j < PATCH; j++)
                    #pragma unroll
                    for (int c = 0; c < CIN; c++) {
                        int off = c*256 + i*16 + j;
                        acc = __fmaf_rn(sm.patch[off], wr[off], acc);
                    }
            g_h[((size_t)b*NTOK + n)*DMODEL + d] = __fadd_rn(__fmul_rn(acc, bn0_s[d]), bn0_b[d]);
        }
        __syncthreads();
    }
    gsync();

    // ---- patch-LIF for t=0 ----
    patch_lif_range(pos, gtid, nth);
    gsync();

    // ---- timestep loop ----
    for (int t = 0; t < TSTEPS; t++) {
        for (int l = 0; l < DEPTH; l++) {
            const size_t wOff  = (size_t)l * DMODEL * DMODEL;
            const size_t w1Off = (size_t)l * MLPD * DMODEL;
            const size_t memD  = (size_t)l * ROWS * DMODEL;
            const size_t memM  = (size_t)l * ROWS * MLPD;
            const float* Wq_l = Wq + wOff;   const float* Wk_l = Wk + wOff;
            const float* Wv_l = Wv + wOff;   const float* Wo_l = Wo + wOff;
            const float* W1_l = W1 + w1Off;  const float* W2_l = W2 + w1Off;
            const float* qs = bnq_s + l*DMODEL, *qb2 = bnq_b + l*DMODEL;
            const float* ks = bnk_s + l*DMODEL, *kb2 = bnk_b + l*DMODEL;
            const float* vs = bnv_s + l*DMODEL, *vb2 = bnv_b + l*DMODEL;
            const float* m1s = bn1_s + l*MLPD,  *m1b = bn1_b + l*MLPD;
            const float* m2s = bn2_s + l*DMODEL, *m2b = bn2_b + l*DMODEL;

            // LN1 (warp per row)
            for (int row = blockIdx.x*8 + wrp; row < ROWS; row += nb*8)
                ln_row_warp(g_y + (size_t)row*DMODEL, ln1_g + l*DMODEL, ln1_b + l*DMODEL,
                            g_xn + (size_t)row*DMODEL);
            gsync();

            // QKV: 3 x 78 = 234 tiles of 64x64
            for (int t5 = blockIdx.x; t5 < 234; t5 += nb) {
                int which = t5 / 78, s = t5 % 78;
                int bm = (s / 6) * 64, bn = (s % 6) * 64;
                if (which == 0)
                    gemm_t64<0>(&sm, g_xn, Wq_l, DMODEL, DMODEL, bm, bn, qs, qb2, g_mq + memD, g_q, 0);
                else if (which == 1)
                    gemm_t64<0>(&sm, g_xn, Wk_l, DMODEL, DMODEL, bm, bn, ks, kb2, g_mk + memD, g_k, 0);
                else
                    gemm_t64<0>(&sm, g_xn, Wv_l, DMODEL, DMODEL, bm, bn, vs, vb2, g_mv + memD, g_v, 0);
            }
            gsync();

            // attention
            for (int item = blockIdx.x; item < 7*32; item += nb) {
                int chunk = item % 7;
                int bh = item / 7;
                int b = bh >> 3, h = bh & 7;
                int n0 = chunk * NCHUNK;
                __syncthreads();
                for (int tt = tid; tt < NTOK*2 + NCHUNK; tt += 256) {
                    int which, n;
                    if (tt < NTOK)        { which = 1; n = tt; }
                    else if (tt < 2*NTOK) { which = 2; n = tt - NTOK; }
                    else                  { which = 0; n = n0 + (tt - 2*NTOK); }
                    const float* src = (which == 0 ? g_q : (which == 1 ? g_k : g_v))
                                       + ((size_t)(b*NTOK + n))*DMODEL + h*HD;
                    unsigned long long bits = 0ull;
                    #pragma unroll
                    for (int j = 0; j < HD; j++)
                        if (src[j] != 0.f) bits |= (1ull << j);
                    if (which == 0)      sm.a.qcb[n - n0] = bits;
                    else if (which == 1) sm.a.kbv[n] = bits;
                    else                 sm.a.vbv[n] = bits;
                }
                __syncthreads();
                // af[n][m] = fl(count * SCALE)
                for (int idx = tid; idx < NCHUNK*NTOK; idx += 256) {
                    int cc = __popcll(sm.a.qcb[idx/NTOK] & sm.a.kbv[idx%NTOK]);
                    sm.a.af[idx/NTOK][idx%NTOK] = __fmul_rn((float)cc, SCALEF);
                }
                __syncthreads();
                // einsum2: per-output serial-m chain; fma(a,vm,acc) == vm? fadd(acc,a) : acc
                {
                    float accv[6];
                    const float* af6[6];
                    int dd6[6];
                    int cnt = 0;
                    for (int it2 = tid; it2 < NCHUNK*HD; it2 += 256) {
                        af6[cnt] = sm.a.af[it2 / HD];
                        dd6[cnt] = it2 % HD;
                        accv[cnt] = 0.f;
                        cnt++;
                    }
                    for (int m = 0; m < NTOK; m++) {
                        unsigned long long vb = sm.a.vbv[m];
                        #pragma unroll
                        for (int i = 0; i < 6; i++) {
                            if (i < cnt) {
                                float a = af6[i][m];
                                if ((vb >> dd6[i]) & 1ull) accv[i] = __fadd_rn(accv[i], a);
                            }
                        }
                    }
                    int ci = 0;
                    for (int it2 = tid; it2 < NCHUNK*HD; it2 += 256) {
                        int n = it2 / HD, d = it2 % HD;
                        g_o[((size_t)(b*NTOK + n0 + n))*DMODEL + h*HD + d] = accv[ci++];
                    }
                }
                __syncthreads();
            }
            gsync();

            // Wo residual: 49x6 = 294 tiles of 16x64
            for (int t5 = blockIdx.x; t5 < 294; t5 += nb) {
                int bm = (t5 / 6) * 16, bn = (t5 % 6) * 64;
                gemm_t16x64<1>(&sm, g_o, Wo_l, DMODEL, DMODEL, bm, bn, 0, 0, 0, 0, g_y);
            }
            gsync();

            // LN2
            for (int row = blockIdx.x*8 + wrp; row < ROWS; row += nb*8)
                ln_row_warp(g_y + (size_t)row*DMODEL, ln2_g + l*DMODEL, ln2_b + l*DMODEL,
                            g_xn + (size_t)row*DMODEL);
            gsync();

            // MLP1: 25x12 = 300 tiles of 32x128
            for (int t5 = blockIdx.x; t5 < 300; t5 += nb) {
                int bm = (t5 / 12) * 32, bn = (t5 % 12) * 128;
                gemm_t32x128<0>(&sm, g_xn, W1_l, MLPD, DMODEL, bm, bn, m1s, m1b, g_m1 + memM, g_s1, 0);
            }
            gsync();

            // MLP2: 49x6 = 294 tiles of 16x64, K=1536
            for (int t5 = blockIdx.x; t5 < 294; t5 += nb) {
                int bm = (t5 / 6) * 16, bn = (t5 % 6) * 64;
                gemm_t16x64<2>(&sm, g_s1, W2_l, DMODEL, MLPD, bm, bn, m2s, m2b, g_m2 + memD, 0, g_y);
            }
            gsync();
        }

        // final LN
        for (int row = blockIdx.x*8 + wrp; row < ROWS; row += nb*8)
            ln_row_warp(g_y + (size_t)row*DMODEL, lnf_g, lnf_b, g_xn + (size_t)row*DMODEL);
        gsync();

        // token-mean pool (serial over n, ascending — major-dim reduce order)
        for (int it = gtid; it < BSZ*DMODEL; it += nth) {
            int b = it / DMODEL, d = it % DMODEL;
            float acc = 0.f;
            for (int n = 0; n < NTOK; n++)
                acc = __fadd_rn(acc, g_xn[((size_t)(b*NTOK + n))*DMODEL + d]);
            g_pool[it] = __fdiv_rn(acc, 196.0f);
        }
        gsync();

        // head logits + LIF (block 0) || patch-LIF for t+1 (other blocks)
        if (blockIdx.x == 0) {
            if (tid < BSZ*NCLS) {
                int b = tid / NCLS, c = tid % NCLS;
                float acc = 0.f;
                for (int d = 0; d < DMODEL; d++)
                    acc = __fmaf_rn(g_pool[b*DMODEL + d], head_w[d*NCLS + c], acc);
                float inp = __fadd_rn(acc, head_b[c]);
                float mm = __fadd_rn(__fmul_rn(BETAF, g_mh[tid]), inp);
                float s = (mm > 1.0f) ? 1.0f : 0.0f;
                g_mh[tid] = __fadd_rn(mm, -s);
                g_acc[tid] += s;
            }
        } else if (t + 1 < TSTEPS) {
            patch_lif_range(pos, (blockIdx.x - 1)*256 + tid, (nb - 1)*256);
        }
        gsync();
    }

    if (blockIdx.x == 0 && tid < BSZ*NCLS)
        out[tid] = __fdiv_rn(g_acc[tid], (float)TSTEPS);
}

// ---------------- host ----------------
extern "C" void kernel_launch(void* const* d_in, const int* in_sizes, int n_in,
                              void* d_out, int out_size)
{
    const float* x       = (const float*)d_in[0];
    const float* conv_w  = (const float*)d_in[1];
    const float* bn0_s   = (const float*)d_in[2];
    const float* bn0_b   = (const float*)d_in[3];
    const float* pos     = (const float*)d_in[4];
    const float* Wq      = (const float*)d_in[5];
    const float* bnq_s   = (const float*)d_in[6];
    const float* bnq_b   = (const float*)d_in[7];
    const float* Wk      = (const float*)d_in[8];
    const float* bnk_s   = (const float*)d_in[9];
    const float* bnk_b   = (const float*)d_in[10];
    const float* Wv      = (const float*)d_in[11];
    const float* bnv_s   = (const float*)d_in[12];
    const float* bnv_b   = (const float*)d_in[13];
    const float* Wo      = (const float*)d_in[14];
    const float* ln1_g   = (const float*)d_in[15];
    const float* ln1_b   = (const float*)d_in[16];
    const float* W1      = (const float*)d_in[17];
    const float* bn1_s   = (const float*)d_in[18];
    const float* bn1_b   = (const float*)d_in[19];
    const float* W2      = (const float*)d_in[20];
    const float* bn2_s   = (const float*)d_in[21];
    const float* bn2_b   = (const float*)d_in[22];
    const float* ln2_g   = (const float*)d_in[23];
    const float* ln2_b   = (const float*)d_in[24];
    const float* lnf_g   = (const float*)d_in[25];
    const float* lnf_b   = (const float*)d_in[26];
    const float* head_w  = (const float*)d_in[27];
    const float* head_b  = (const float*)d_in[28];
    float* out = (float*)d_out;

    int dev = 0;
    cudaGetDevice(&dev);
    int nsm = 0;
    cudaDeviceGetAttribute(&nsm, cudaDevAttrMultiProcessorCount, dev);
    int bpm = 0;
    cudaOccupancyMaxActiveBlocksPerMultiprocessor(&bpm, mega, 256, 0);
    if (bpm < 1) bpm = 1;
    if (bpm > 2) bpm = 2;
    int nblk = nsm * bpm;

    mega<<<nblk, 256>>>(x, conv_w, bn0_s, bn0_b, pos,
                        Wq, bnq_s, bnq_b, Wk, bnk_s, bnk_b, Wv, bnv_s, bnv_b, Wo,
                        ln1_g, ln1_b, W1, bn1_s, bn1_b, W2, bn2_s, bn2_b,
                        ln2_g, ln2_b, lnf_g, lnf_b, head_w, head_b, out);
}

// round 12
// speedup vs baseline: 1.4908x; 1.0047x over previous
#include <cuda_runtime.h>
#include <math.h>
#include <stdint.h>

// ---------------- problem constants ----------------
#define BSZ    4
#define CIN    3
#define IMG    224
#define PATCH  16
#define DMODEL 384
#define DEPTH  4
#define NHEAD  8
#define HD     48
#define MLPD   1536
#define NCLS   5
#define TSTEPS 25
#define NTOK   196
#define ROWS   (BSZ*NTOK) // 784
#define HP     14
#define BETAF  0.9f
#define EPSF   1e-5f
#define SCALEF 0.14433756729740643f  // 48^-0.5
#define NCHUNK 28                     // 196 = 7*28

// ---------------- device state ----------------
__device__ float g_h   [ROWS*DMODEL];
__device__ float g_y   [ROWS*DMODEL];
__device__ float g_xn  [ROWS*DMODEL];
__device__ float g_q   [ROWS*DMODEL];
__device__ float g_k   [ROWS*DMODEL];
__device__ float g_v   [ROWS*DMODEL];
__device__ float g_o   [ROWS*DMODEL];
__device__ float g_s1  [ROWS*MLPD];
__device__ float g_pool[BSZ*DMODEL];
__device__ float g_mpe [ROWS*DMODEL];
__device__ float g_mq  [DEPTH*ROWS*DMODEL];
__device__ float g_mk  [DEPTH*ROWS*DMODEL];
__device__ float g_mv  [DEPTH*ROWS*DMODEL];
__device__ float g_m1  [DEPTH*ROWS*MLPD];
__device__ float g_m2  [DEPTH*ROWS*DMODEL];
__device__ float g_mh  [BSZ*NCLS];
__device__ float g_acc [BSZ*NCLS];

// software grid barrier state
__device__ unsigned g_arrive;
__device__ unsigned g_gen;

__device__ __forceinline__ void gsync()
{
    __syncthreads();
    if (threadIdx.x == 0) {
        __threadfence();
        unsigned gen = *(volatile unsigned*)&g_gen;
        unsigned nb = gridDim.x;
        if (atomicAdd(&g_arrive, 1u) == nb - 1u) {
            g_arrive = 0u;
            __threadfence();
            *(volatile unsigned*)&g_gen = gen + 1u;
        } else {
            while (*(volatile unsigned*)&g_gen == gen) { __nanosleep(64); }
        }
    }
    __syncthreads();
}

// ---------------- packed f32x2 helpers (each lane correctly rounded == __fmaf_rn) ----------------
__device__ __forceinline__ void ffma2(uint64_t& acc, uint64_t a, uint64_t b)
{
    asm("fma.rn.f32x2 %0, %1, %2, %0;" : "+l"(acc) : "l"(a), "l"(b));
}
__device__ __forceinline__ uint64_t pk2(float x)
{
    uint64_t r; asm("mov.b64 %0, {%1, %1};" : "=l"(r) : "f"(x)); return r;
}
__device__ __forceinline__ float2 upk(uint64_t v)
{
    float lo, hi; asm("mov.b64 {%0, %1}, %2;" : "=f"(lo), "=f"(hi) : "l"(v));
    return make_float2(lo, hi);
}

// ---------------- shared memory union ----------------
struct SmemU {
    union {
        float patch[CIN*PATCH*PATCH];                              // conv
        struct { float As[2][16][68];  float Bs[2][16][68];  } g;  // 64x64
        struct { float As[2][16][36];  float Bs[2][16][132]; } h;  // 32x128
        struct { float As[2][16][17];  float Bs[2][16][68];  } w2; // 16x64
        struct {
            unsigned long long qcb[NCHUNK];
            unsigned long long kbv[NTOK];
            unsigned long long vbv[NTOK];
            float af[NCHUNK][197];                                 // fl(count*SCALE)
        } a;                                                       // attn ~25.4KB
    };
};

// ---------------- epilogue ----------------
// MODE 0: LIF -> spike   MODE 1: yout += acc   MODE 2: LIF -> yout += spike
template<int MODE>
__device__ __forceinline__ void ep_one(int m, int n, int N, float vv,
        const float* __restrict__ scale, const float* __restrict__ bias,
        float* __restrict__ mem, float* __restrict__ spk, float* __restrict__ yout)
{
    size_t idx = (size_t)m*N + n;
    if (MODE == 1) {
        yout[idx] = __fadd_rn(yout[idx], vv);
    } else {
        vv = __fadd_rn(__fmul_rn(vv, scale[n]), bias[n]);
        float mm = __fadd_rn(__fmul_rn(BETAF, mem[idx]), vv);
        float s = (mm > 1.0f) ? 1.0f : 0.0f;
        mem[idx] = __fadd_rn(mm, -s);
        if (MODE == 0) spk[idx] = s;
        else           yout[idx] = __fadd_rn(yout[idx], s);
    }
}

// ---------------- gemm 64x64 tile, 4x4 micro (FFMA2), reg-prefetch pipelined (QKV) ----------------
template<int MODE>
__device__ __forceinline__ void gemm_t64(SmemU* sm,
        const float* __restrict__ A, const float* __restrict__ W,
        int N, int K, int bm, int bn,
        const float* __restrict__ scale, const float* __restrict__ bias,
        float* __restrict__ mem, float* __restrict__ spk, float* __restrict__ yout)
{
    const int tid = threadIdx.x;
    const int tx = tid & 15;
    const int ty = tid >> 4;
    const int lr = tid >> 2;         // 0..63
    const int lk = (tid & 3) << 2;   // 0,4,8,12
    const int ar = bm + lr;
    const bool aok = (ar < ROWS);
    const float* aptr = A + (size_t)(aok ? ar : 0)*K + lk;
    const float* bptr = W + (size_t)(bn + lr)*K + lk;

    // accp[rp][c]: packed rows (ty*4+2rp, ty*4+2rp+1), column tx*4+c
    uint64_t accp[2][4];
    #pragma unroll
    for (int i = 0; i < 2; i++)
        #pragma unroll
        for (int j = 0; j < 4; j++) accp[i][j] = 0ull;

    const int nch = K >> 4;
    float4 av = aok ? *reinterpret_cast<const float4*>(aptr) : make_float4(0.f,0.f,0.f,0.f);
    float4 bv = *reinterpret_cast<const float4*>(bptr);
    sm->g.As[0][lk+0][lr]=av.x; sm->g.As[0][lk+1][lr]=av.y;
    sm->g.As[0][lk+2][lr]=av.z; sm->g.As[0][lk+3][lr]=av.w;
    sm->g.Bs[0][lk+0][lr]=bv.x; sm->g.Bs[0][lk+1][lr]=bv.y;
    sm->g.Bs[0][lk+2][lr]=bv.z; sm->g.Bs[0][lk+3][lr]=bv.w;
    __syncthreads();

    for (int c = 0; c < nch; c++) {
        const int buf = c & 1;
        float4 av2, bv2;
        const bool more = (c + 1 < nch);
        if (more) {
            av2 = aok ? *reinterpret_cast<const float4*>(aptr + (c+1)*16)
                      : make_float4(0.f,0.f,0.f,0.f);
            bv2 = *reinterpret_cast<const float4*>(bptr + (c+1)*16);
        }
        #pragma unroll
        for (int kk = 0; kk < 16; kk++) {   // strictly ascending k; single chain per output
            ulonglong2 ap = *reinterpret_cast<const ulonglong2*>(&sm->g.As[buf][kk][ty*4]);
            float4 b = *reinterpret_cast<const float4*>(&sm->g.Bs[buf][kk][tx*4]);
            uint64_t bx = pk2(b.x), by = pk2(b.y), bz = pk2(b.z), bw = pk2(b.w);
            ffma2(accp[0][0], ap.x, bx); ffma2(accp[0][1], ap.x, by);
            ffma2(accp[0][2], ap.x, bz); ffma2(accp[0][3], ap.x, bw);
            ffma2(accp[1][0], ap.y, bx); ffma2(accp[1][1], ap.y, by);
            ffma2(accp[1][2], ap.y, bz); ffma2(accp[1][3], ap.y, bw);
        }
        if (more) {
            const int nbuf = buf ^ 1;
            sm->g.As[nbuf][lk+0][lr]=av2.x; sm->g.As[nbuf][lk+1][lr]=av2.y;
            sm->g.As[nbuf][lk+2][lr]=av2.z; sm->g.As[nbuf][lk+3][lr]=av2.w;
            sm->g.Bs[nbuf][lk+0][lr]=bv2.x; sm->g.Bs[nbuf][lk+1][lr]=bv2.y;
            sm->g.Bs[nbuf][lk+2][lr]=bv2.z; sm->g.Bs[nbuf][lk+3][lr]=bv2.w;
        }
        __syncthreads();
    }
    #pragma unroll
    for (int rp = 0; rp < 2; rp++) {
        #pragma unroll
        for (int j = 0; j < 4; j++) {
            float2 v = upk(accp[rp][j]);
            int m0 = bm + ty*4 + rp*2;
            int n  = bn + tx*4 + j;
            if (m0 < ROWS)     ep_one<MODE>(m0,     n, N, v.x, scale, bias, mem, spk, yout);
            if (m0 + 1 < ROWS) ep_one<MODE>(m0 + 1, n, N, v.y, scale, bias, mem, spk, yout);
        }
    }
}

// ---------------- gemm 32x128 tile, 4x4 micro (FFMA2), pipelined (MLP1) ----------------
template<int MODE>
__device__ __forceinline__ void gemm_t32x128(SmemU* sm,
        const float* __restrict__ A, const float* __restrict__ W,
        int N, int K, int bm, int bn,
        const float* __restrict__ scale, const float* __restrict__ bias,
        float* __restrict__ mem, float* __restrict__ spk, float* __restrict__ yout)
{
    const int tid = threadIdx.x;
    const int tx = tid & 31;   // cols tx*4 (0..127)
    const int ty = tid >> 5;   // rows ty*4 (0..31)
    const int lrow = tid >> 2;
    const int lkq  = (tid & 3) << 2;
    const bool aload = (tid < 128);
    const int ar = bm + lrow;
    const bool aok = aload && (ar < ROWS);
    const float* aptr = A + (size_t)(aok ? ar : 0)*K + lkq;
    const float* bptr0 = W + (size_t)(bn + lrow)*K + lkq;
    const float* bptr1 = W + (size_t)(bn + 64 + lrow)*K + lkq;

    uint64_t accp[2][4];
    #pragma unroll
    for (int i = 0; i < 2; i++)
        #pragma unroll
        for (int j = 0; j < 4; j++) accp[i][j] = 0ull;

    const int nch = K >> 4;
    float4 av = aok ? *reinterpret_cast<const float4*>(aptr) : make_float4(0.f,0.f,0.f,0.f);
    float4 bva = *reinterpret_cast<const float4*>(bptr0);
    float4 bvb = *reinterpret_cast<const float4*>(bptr1);
    if (aload) {
        sm->h.As[0][lkq+0][lrow]=av.x; sm->h.As[0][lkq+1][lrow]=av.y;
        sm->h.As[0][lkq+2][lrow]=av.z; sm->h.As[0][lkq+3][lrow]=av.w;
    }
    sm->h.Bs[0][lkq+0][lrow]=bva.x;    sm->h.Bs[0][lkq+1][lrow]=bva.y;
    sm->h.Bs[0][lkq+2][lrow]=bva.z;    sm->h.Bs[0][lkq+3][lrow]=bva.w;
    sm->h.Bs[0][lkq+0][64+lrow]=bvb.x; sm->h.Bs[0][lkq+1][64+lrow]=bvb.y;
    sm->h.Bs[0][lkq+2][64+lrow]=bvb.z; sm->h.Bs[0][lkq+3][64+lrow]=bvb.w;
    __syncthreads();

    for (int c = 0; c < nch; c++) {
        const int buf = c & 1;
        float4 av2, b2a, b2b;
        const bool more = (c + 1 < nch);
        if (more) {
            av2 = aok ? *reinterpret_cast<const float4*>(aptr + (c+1)*16)
                      : make_float4(0.f,0.f,0.f,0.f);
            b2a = *reinterpret_cast<const float4*>(bptr0 + (c+1)*16);
            b2b = *reinterpret_cast<const float4*>(bptr1 + (c+1)*16);
        }
        #pragma unroll
        for (int kk = 0; kk < 16; kk++) {
            ulonglong2 ap = *reinterpret_cast<const ulonglong2*>(&sm->h.As[buf][kk][ty*4]);
            float4 b = *reinterpret_cast<const float4*>(&sm->h.Bs[buf][kk][tx*4]);
            uint64_t bx = pk2(b.x), by = pk2(b.y), bz = pk2(b.z), bw = pk2(b.w);
            ffma2(accp[0][0], ap.x, bx); ffma2(accp[0][1], ap.x, by);
            ffma2(accp[0][2], ap.x, bz); ffma2(accp[0][3], ap.x, bw);
            ffma2(accp[1][0], ap.y, bx); ffma2(accp[1][1], ap.y, by);
            ffma2(accp[1][2], ap.y, bz); ffma2(accp[1][3], ap.y, bw);
        }
        if (more) {
            const int nbuf = buf ^ 1;
            if (aload) {
                sm->h.As[nbuf][lkq+0][lrow]=av2.x; sm->h.As[nbuf][lkq+1][lrow]=av2.y;
                sm->h.As[nbuf][lkq+2][lrow]=av2.z; sm->h.As[nbuf][lkq+3][lrow]=av2.w;
            }
            sm->h.Bs[nbuf][lkq+0][lrow]=b2a.x;    sm->h.Bs[nbuf][lkq+1][lrow]=b2a.y;
            sm->h.Bs[nbuf][lkq+2][lrow]=b2a.z;    sm->h.Bs[nbuf][lkq+3][lrow]=b2a.w;
            sm->h.Bs[nbuf][lkq+0][64+lrow]=b2b.x; sm->h.Bs[nbuf][lkq+1][64+lrow]=b2b.y;
            sm->h.Bs[nbuf][lkq+2][64+lrow]=b2b.z; sm->h.Bs[nbuf][lkq+3][64+lrow]=b2b.w;
        }
        __syncthreads();
    }
    #pragma unroll
    for (int rp = 0; rp < 2; rp++) {
        #pragma unroll
        for (int j = 0; j < 4; j++) {
            float2 v = upk(accp[rp][j]);
            int m0 = bm + ty*4 + rp*2;
            int n  = bn + tx*4 + j;
            if (m0 < ROWS)     ep_one<MODE>(m0,     n, N, v.x, scale, bias, mem, spk, yout);
            if (m0 + 1 < ROWS) ep_one<MODE>(m0 + 1, n, N, v.y, scale, bias, mem, spk, yout);
        }
    }
}

// ---------------- gemm 16x64 tile, 1x4 micro (FFMA2), pipelined (Wo, MLP2) ----------------
template<int MODE>
__device__ __forceinline__ void gemm_t16x64(SmemU* sm,
        const float* __restrict__ A, const float* __restrict__ W,
        int N, int K, int bm, int bn,
        const float* __restrict__ scale, const float* __restrict__ bias,
        float* __restrict__ mem, float* __restrict__ spk, float* __restrict__ yout)
{
    const int tid = threadIdx.x;
    const int tx = tid & 15;   // col group
    const int my = tid >> 4;   // row 0..15
    const int lrow = tid >> 2;
    const int lkq  = (tid & 3) << 2;
    const bool aload = (tid < 64);
    const float* aptr = A + (size_t)(bm + (aload ? lrow : 0))*K + lkq;
    const float* bptr = W + (size_t)(bn + lrow)*K + lkq;

    uint64_t acc01 = 0ull, acc23 = 0ull;   // cols (0,1) and (2,3)

    const int nch = K >> 4;
    float4 av, bv;
    if (aload) av = *reinterpret_cast<const float4*>(aptr);
    bv = *reinterpret_cast<const float4*>(bptr);
    if (aload) {
        sm->w2.As[0][lkq+0][lrow]=av.x; sm->w2.As[0][lkq+1][lrow]=av.y;
        sm->w2.As[0][lkq+2][lrow]=av.z; sm->w2.As[0][lkq+3][lrow]=av.w;
    }
    sm->w2.Bs[0][lkq+0][lrow]=bv.x; sm->w2.Bs[0][lkq+1][lrow]=bv.y;
    sm->w2.Bs[0][lkq+2][lrow]=bv.z; sm->w2.Bs[0][lkq+3][lrow]=bv.w;
    __syncthreads();

    for (int c = 0; c < nch; c++) {
        const int buf = c & 1;
        float4 av2, bv2;
        const bool more = (c + 1 < nch);
        if (more) {
            if (aload) av2 = *reinterpret_cast<const float4*>(aptr + (c+1)*16);
            bv2 = *reinterpret_cast<const float4*>(bptr + (c+1)*16);
        }
        #pragma unroll
        for (int kk = 0; kk < 16; kk++) {   // strictly ascending k
            uint64_t ad = pk2(sm->w2.As[buf][kk][my]);
            ulonglong2 bp = *reinterpret_cast<const ulonglong2*>(&sm->w2.Bs[buf][kk][tx*4]);
            ffma2(acc01, ad, bp.x);
            ffma2(acc23, ad, bp.y);
        }
        if (more) {
            const int nbuf = buf ^ 1;
            if (aload) {
                sm->w2.As[nbuf][lkq+0][lrow]=av2.x; sm->w2.As[nbuf][lkq+1][lrow]=av2.y;
                sm->w2.As[nbuf][lkq+2][lrow]=av2.z; sm->w2.As[nbuf][lkq+3][lrow]=av2.w;
            }
            sm->w2.Bs[nbuf][lkq+0][lrow]=bv2.x; sm->w2.Bs[nbuf][lkq+1][lrow]=bv2.y;
            sm->w2.Bs[nbuf][lkq+2][lrow]=bv2.z; sm->w2.Bs[nbuf][lkq+3][lrow]=bv2.w;
        }
        __syncthreads();
    }
    const int m = bm + my;   // always < ROWS (784 = 49*16)
    float2 v01 = upk(acc01);
    float2 v23 = upk(acc23);
    ep_one<MODE>(m, bn + tx*4 + 0, N, v01.x, scale, bias, mem, spk, yout);
    ep_one<MODE>(m, bn + tx*4 + 1, N, v01.y, scale, bias, mem, spk, yout);
    ep_one<MODE>(m, bn + tx*4 + 2, N, v23.x, scale, bias, mem, spk, yout);
    ep_one<MODE>(m, bn + tx*4 + 3, N, v23.y, scale, bias, mem, spk, yout);
}

// ---------------- layernorm row, XLA:CPU vectorized-reduce order ----------------
__device__ __forceinline__ void ln_row_warp(const float* __restrict__ rin,
        const float* __restrict__ g, const float* __restrict__ bta, float* __restrict__ out)
{
    const unsigned fm = 0xffffffffu;
    int lane = threadIdx.x & 31;
    float a = 0.f;
    if (lane < 4) {
        for (int t2 = 0; t2 < 96; t2++) a = __fadd_rn(a, rin[4*t2 + lane]);
    }
    float a0 = __shfl_sync(fm, a, 0), a1 = __shfl_sync(fm, a, 1);
    float a2 = __shfl_sync(fm, a, 2), a3 = __shfl_sync(fm, a, 3);
    float mean = __fdiv_rn(__fadd_rn(__fadd_rn(a0, a2), __fadd_rn(a1, a3)), 384.0f);

    float b = 0.f;
    if (lane < 4) {
        for (int t2 = 0; t2 < 96; t2++) {
            float d = __fadd_rn(rin[4*t2 + lane], -mean);
            b = __fadd_rn(b, __fmul_rn(d, d));
        }
    }
    float b0 = __shfl_sync(fm, b, 0), b1 = __shfl_sync(fm, b, 1);
    float b2 = __shfl_sync(fm, b, 2), b3 = __shfl_sync(fm, b, 3);
    float var = __fdiv_rn(__fadd_rn(__fadd_rn(b0, b2), __fadd_rn(b1, b3)), 384.0f);
    float inv = __fdiv_rn(1.0f, __fsqrt_rn(__fadd_rn(var, EPSF)));

    for (int d = lane; d < DMODEL; d += 32) {
        float dv = __fadd_rn(rin[d], -mean);
        out[d] = __fadd_rn(__fmul_rn(__fmul_rn(dv, inv), g[d]), bta[d]);
    }
}

// ---------------- patch-embed LIF + pos (strided range) ----------------
__device__ __forceinline__ void patch_lif_range(const float* __restrict__ pos, int start, int stride)
{
    for (int i = start; i < ROWS*DMODEL; i += stride) {
        float mm = __fadd_rn(__fmul_rn(BETAF, g_mpe[i]), g_h[i]);
        float s = (mm > 1.0f) ? 1.0f : 0.0f;
        g_mpe[i] = __fadd_rn(mm, -s);
        g_y[i] = __fadd_rn(s, pos[i % (NTOK*DMODEL)]);
    }
}

// ---------------- zero helper ----------------
__device__ __forceinline__ void zero_arr(float* p, int n, int gtid, int nth)
{
    for (int i = gtid; i < n; i += nth) p[i] = 0.f;
}

// ---------------- the megakernel ----------------
__global__ void __launch_bounds__(256, 2) mega(
    const float* __restrict__ x,      const float* __restrict__ conv_w,
    const float* __restrict__ bn0_s,  const float* __restrict__ bn0_b,
    const float* __restrict__ pos,
    const float* __restrict__ Wq,     const float* __restrict__ bnq_s, const float* __restrict__ bnq_b,
    const float* __restrict__ Wk,     const float* __restrict__ bnk_s, const float* __restrict__ bnk_b,
    const float* __restrict__ Wv,     const float* __restrict__ bnv_s, const float* __restrict__ bnv_b,
    const float* __restrict__ Wo,
    const float* __restrict__ ln1_g,  const float* __restrict__ ln1_b,
    const float* __restrict__ W1,     const float* __restrict__ bn1_s, const float* __restrict__ bn1_b,
    const float* __restrict__ W2,     const float* __restrict__ bn2_s, const float* __restrict__ bn2_b,
    const float* __restrict__ ln2_g,  const float* __restrict__ ln2_b,
    const float* __restrict__ lnf_g,  const float* __restrict__ lnf_b,
    const float* __restrict__ head_w, const float* __restrict__ head_b,
    float* __restrict__ out)
{
    __shared__ SmemU sm;
    const int nb  = gridDim.x;
    const int tid = threadIdx.x;
    const int wrp = tid >> 5;
    const int gtid = blockIdx.x * 256 + tid;
    const int nth  = nb * 256;

    // ---- zero persistent state ----
    zero_arr(g_mpe, ROWS*DMODEL, gtid, nth);
    zero_arr(g_mq,  DEPTH*ROWS*DMODEL, gtid, nth);
    zero_arr(g_mk,  DEPTH*ROWS*DMODEL, gtid, nth);
    zero_arr(g_mv,  DEPTH*ROWS*DMODEL, gtid, nth);
    zero_arr(g_m1,  DEPTH*ROWS*MLPD, gtid, nth);
    zero_arr(g_m2,  DEPTH*ROWS*DMODEL, gtid, nth);
    zero_arr(g_mh,  BSZ*NCLS, gtid, nth);
    zero_arr(g_acc, BSZ*NCLS, gtid, nth);

    // ---- conv patch embed (once); Eigen tap order (kh, kw, c), c minor ----
    for (int item = blockIdx.x; item < ROWS; item += nb) {
        int b = item / NTOK, n = item % NTOK;
        int py = n / HP, px = n % HP;
        for (int idx = tid; idx < 768; idx += 256) {
            int c = idx >> 8; int rem = idx & 255; int i = rem >> 4; int j = rem & 15;
            sm.patch[idx] = x[(((size_t)b*CIN + c)*IMG + (py*PATCH + i))*IMG + (px*PATCH + j)];
        }
        __syncthreads();
        for (int d = tid; d < DMODEL; d += 256) {
            const float* wr = conv_w + (size_t)d*768;
            float acc = 0.f;
            for (int i = 0; i < PATCH; i++)
                for (int j = 0; j < PATCH; j++)
                    #pragma unroll
                    for (int c = 0; c < CIN; c++) {
                        int off = c*256 + i*16 + j;
                        acc = __fmaf_rn(sm.patch[off], wr[off], acc);
                    }
            g_h[((size_t)b*NTOK + n)*DMODEL + d] = __fadd_rn(__fmul_rn(acc, bn0_s[d]), bn0_b[d]);
        }
        __syncthreads();
    }
    gsync();

    // ---- patch-LIF for t=0 ----
    patch_lif_range(pos, gtid, nth);
    gsync();

    // ---- timestep loop ----
    for (int t = 0; t < TSTEPS; t++) {
        for (int l = 0; l < DEPTH; l++) {
            const size_t wOff  = (size_t)l * DMODEL * DMODEL;
            const size_t w1Off = (size_t)l * MLPD * DMODEL;
            const size_t memD  = (size_t)l * ROWS * DMODEL;
            const size_t memM  = (size_t)l * ROWS * MLPD;
            const float* Wq_l = Wq + wOff;   const float* Wk_l = Wk + wOff;
            const float* Wv_l = Wv + wOff;   const float* Wo_l = Wo + wOff;
            const float* W1_l = W1 + w1Off;  const float* W2_l = W2 + w1Off;
            const float* qs = bnq_s + l*DMODEL, *qb2 = bnq_b + l*DMODEL;
            const float* ks = bnk_s + l*DMODEL, *kb2 = bnk_b + l*DMODEL;
            const float* vs = bnv_s + l*DMODEL, *vb2 = bnv_b + l*DMODEL;
            const float* m1s = bn1_s + l*MLPD,  *m1b = bn1_b + l*MLPD;
            const float* m2s = bn2_s + l*DMODEL, *m2b = bn2_b + l*DMODEL;

            // LN1 (warp per row)
            for (int row = blockIdx.x*8 + wrp; row < ROWS; row += nb*8)
                ln_row_warp(g_y + (size_t)row*DMODEL, ln1_g + l*DMODEL, ln1_b + l*DMODEL,
                            g_xn + (size_t)row*DMODEL);
            gsync();

            // QKV: 3 x 78 = 234 tiles of 64x64
            for (int t5 = blockIdx.x; t5 < 234; t5 += nb) {
                int which = t5 / 78, s = t5 % 78;
                int bm = (s / 6) * 64, bn = (s % 6) * 64;
                if (which == 0)
                    gemm_t64<0>(&sm, g_xn, Wq_l, DMODEL, DMODEL, bm, bn, qs, qb2, g_mq + memD, g_q, 0);
                else if (which == 1)
                    gemm_t64<0>(&sm, g_xn, Wk_l, DMODEL, DMODEL, bm, bn, ks, kb2, g_mk + memD, g_k, 0);
                else
                    gemm_t64<0>(&sm, g_xn, Wv_l, DMODEL, DMODEL, bm, bn, vs, vb2, g_mv + memD, g_v, 0);
            }
            gsync();

            // attention
            for (int item = blockIdx.x; item < 7*32; item += nb) {
                int chunk = item % 7;
                int bh = item / 7;
                int b = bh >> 3, h = bh & 7;
                int n0 = chunk * NCHUNK;
                __syncthreads();
                for (int tt = tid; tt < NTOK*2 + NCHUNK; tt += 256) {
                    int which, n;
                    if (tt < NTOK)        { which = 1; n = tt; }
                    else if (tt < 2*NTOK) { which = 2; n = tt - NTOK; }
                    else                  { which = 0; n = n0 + (tt - 2*NTOK); }
                    const float* src = (which == 0 ? g_q : (which == 1 ? g_k : g_v))
                                       + ((size_t)(b*NTOK + n))*DMODEL + h*HD;
                    unsigned long long bits = 0ull;
                    #pragma unroll
                    for (int j = 0; j < HD; j++)
                        if (src[j] != 0.f) bits |= (1ull << j);
                    if (which == 0)      sm.a.qcb[n - n0] = bits;
                    else if (which == 1) sm.a.kbv[n] = bits;
                    else                 sm.a.vbv[n] = bits;
                }
                __syncthreads();
                // af[n][m] = fl(count * SCALE)
                for (int idx = tid; idx < NCHUNK*NTOK; idx += 256) {
                    int cc = __popcll(sm.a.qcb[idx/NTOK] & sm.a.kbv[idx%NTOK]);
                    sm.a.af[idx/NTOK][idx%NTOK] = __fmul_rn((float)cc, SCALEF);
                }
                __syncthreads();
                // einsum2: per-output serial-m chain; fma(a,vm,acc) == vm? fadd(acc,a) : acc
                {
                    float accv[6];
                    const float* af6[6];
                    int dd6[6];
                    int cnt = 0;
                    for (int it2 = tid; it2 < NCHUNK*HD; it2 += 256) {
                        af6[cnt] = sm.a.af[it2 / HD];
                        dd6[cnt] = it2 % HD;
                        accv[cnt] = 0.f;
                        cnt++;
                    }
                    for (int m = 0; m < NTOK; m++) {
                        unsigned long long vb = sm.a.vbv[m];
                        #pragma unroll
                        for (int i = 0; i < 6; i++) {
                            if (i < cnt) {
                                float a = af6[i][m];
                                if ((vb >> dd6[i]) & 1ull) accv[i] = __fadd_rn(accv[i], a);
                            }
                        }
                    }
                    int ci = 0;
                    for (int it2 = tid; it2 < NCHUNK*HD; it2 += 256) {
                        int n = it2 / HD, d = it2 % HD;
                        g_o[((size_t)(b*NTOK + n0 + n))*DMODEL + h*HD + d] = accv[ci++];
                    }
                }
                __syncthreads();
            }
            gsync();

            // Wo residual: 49x6 = 294 tiles of 16x64
            for (int t5 = blockIdx.x; t5 < 294; t5 += nb) {
                int bm = (t5 / 6) * 16, bn = (t5 % 6) * 64;
                gemm_t16x64<1>(&sm, g_o, Wo_l, DMODEL, DMODEL, bm, bn, 0, 0, 0, 0, g_y);
            }
            gsync();

            // LN2
            for (int row = blockIdx.x*8 + wrp; row < ROWS; row += nb*8)
                ln_row_warp(g_y + (size_t)row*DMODEL, ln2_g + l*DMODEL, ln2_b + l*DMODEL,
                            g_xn + (size_t)row*DMODEL);
            gsync();

            // MLP1: 25x12 = 300 tiles of 32x128
            for (int t5 = blockIdx.x; t5 < 300; t5 += nb) {
                int bm = (t5 / 12) * 32, bn = (t5 % 12) * 128;
                gemm_t32x128<0>(&sm, g_xn, W1_l, MLPD, DMODEL, bm, bn, m1s, m1b, g_m1 + memM, g_s1, 0);
            }
            gsync();

            // MLP2: 49x6 = 294 tiles of 16x64, K=1536
            for (int t5 = blockIdx.x; t5 < 294; t5 += nb) {
                int bm = (t5 / 6) * 16, bn = (t5 % 6) * 64;
                gemm_t16x64<2>(&sm, g_s1, W2_l, DMODEL, MLPD, bm, bn, m2s, m2b, g_m2 + memD, 0, g_y);
            }
            gsync();
        }

        // final LN
        for (int row = blockIdx.x*8 + wrp; row < ROWS; row += nb*8)
            ln_row_warp(g_y + (size_t)row*DMODEL, lnf_g, lnf_b, g_xn + (size_t)row*DMODEL);
        gsync();

        // token-mean pool (serial over n, ascending — major-dim reduce order)
        for (int it = gtid; it < BSZ*DMODEL; it += nth) {
            int b = it / DMODEL, d = it % DMODEL;
            float acc = 0.f;
            for (int n = 0; n < NTOK; n++)
                acc = __fadd_rn(acc, g_xn[((size_t)(b*NTOK + n))*DMODEL + d]);
            g_pool[it] = __fdiv_rn(acc, 196.0f);
        }
        gsync();

        // head logits + LIF (block 0) || patch-LIF for t+1 (other blocks)
        if (blockIdx.x == 0) {
            if (tid < BSZ*NCLS) {
                int b = tid / NCLS, c = tid % NCLS;
                float acc = 0.f;
                for (int d = 0; d < DMODEL; d++)
                    acc = __fmaf_rn(g_pool[b*DMODEL + d], head_w[d*NCLS + c], acc);
                float inp = __fadd_rn(acc, head_b[c]);
                float mm = __fadd_rn(__fmul_rn(BETAF, g_mh[tid]), inp);
                float s = (mm > 1.0f) ? 1.0f : 0.0f;
                g_mh[tid] = __fadd_rn(mm, -s);
                g_acc[tid] += s;
            }
        } else if (t + 1 < TSTEPS) {
            patch_lif_range(pos, (blockIdx.x - 1)*256 + tid, (nb - 1)*256);
        }
        gsync();
    }

    if (blockIdx.x == 0 && tid < BSZ*NCLS)
        out[tid] = __fdiv_rn(g_acc[tid], (float)TSTEPS);
}

// ---------------- host ----------------
extern "C" void kernel_launch(void* const* d_in, const int* in_sizes, int n_in,
                              void* d_out, int out_size)
{
    const float* x       = (const float*)d_in[0];
    const float* conv_w  = (const float*)d_in[1];
    const float* bn0_s   = (const float*)d_in[2];
    const float* bn0_b   = (const float*)d_in[3];
    const float* pos     = (const float*)d_in[4];
    const float* Wq      = (const float*)d_in[5];
    const float* bnq_s   = (const float*)d_in[6];
    const float* bnq_b   = (const float*)d_in[7];
    const float* Wk      = (const float*)d_in[8];
    const float* bnk_s   = (const float*)d_in[9];
    const float* bnk_b   = (const float*)d_in[10];
    const float* Wv      = (const float*)d_in[11];
    const float* bnv_s   = (const float*)d_in[12];
    const float* bnv_b   = (const float*)d_in[13];
    const float* Wo      = (const float*)d_in[14];
    const float* ln1_g   = (const float*)d_in[15];
    const float* ln1_b   = (const float*)d_in[16];
    const float* W1      = (const float*)d_in[17];
    const float* bn1_s   = (const float*)d_in[18];
    const float* bn1_b   = (const float*)d_in[19];
    const float* W2      = (const float*)d_in[20];
    const float* bn2_s   = (const float*)d_in[21];
    const float* bn2_b   = (const float*)d_in[22];
    const float* ln2_g   = (const float*)d_in[23];
    const float* ln2_b   = (const float*)d_in[24];
    const float* lnf_g   = (const float*)d_in[25];
    const float* lnf_b   = (const float*)d_in[26];
    const float* head_w  = (const float*)d_in[27];
    const float* head_b  = (const float*)d_in[28];
    float* out = (float*)d_out;

    int dev = 0;
    cudaGetDevice(&dev);
    int nsm = 0;
    cudaDeviceGetAttribute(&nsm, cudaDevAttrMultiProcessorCount, dev);
    int bpm = 0;
    cudaOccupancyMaxActiveBlocksPerMultiprocessor(&bpm, mega, 256, 0);
    if (bpm < 1) bpm = 1;
    if (bpm > 2) bpm = 2;
    int nblk = nsm * bpm;

    mega<<<nblk, 256>>>(x, conv_w, bn0_s, bn0_b, pos,
                        Wq, bnq_s, bnq_b, Wk, bnk_s, bnk_b, Wv, bnv_s, bnv_b, Wo,
                        ln1_g, ln1_b, W1, bn1_s, bn1_b, W2, bn2_s, bn2_b,
                        ln2_g, ln2_b, lnf_g, lnf_b, head_w, head_b, out);
}